// round 13
// baseline (speedup 1.0000x reference)
#include <cuda_runtime.h>

#define BB 32
#define PP 196
#define NH 14

static __device__ unsigned int g_idx1[BB * PP * 64];
static __device__ float        g_out1[BB * PP * 256];
static __device__ unsigned int g_idx2[BB * PP * 64];
static __device__ float        g_out2[BB * PP * 256];
static __device__ unsigned int g_idx3[BB * PP * 16];

__device__ __forceinline__ void cp16(unsigned int dst, const void* src) {
    asm volatile("cp.async.cg.shared.global [%0], [%1], 16;\n" :: "r"(dst), "l"(src));
}
__device__ __forceinline__ void cpcommit() { asm volatile("cp.async.commit_group;\n" ::: "memory"); }
__device__ __forceinline__ void cpwait0()  { asm volatile("cp.async.wait_group 0;\n" ::: "memory"); }
__device__ __forceinline__ void cpwait1()  { asm volatile("cp.async.wait_group 1;\n" ::: "memory"); }

// ---------------- encode1: smem-staged x tile, FMA dots. dyn smem 57344 ----------------
__global__ void __launch_bounds__(256) k_encode1(const float* __restrict__ x,
                                                 const float* __restrict__ cent) {
    extern __shared__ float xs[];   // [c][w]: 1024*14 floats
    const int b = blockIdx.y, h = blockIdx.x, cb = threadIdx.x;
    for (int i = cb; i < 1024 * 14; i += 256) {
        const int c = i / 14, w = i % 14;
        xs[i] = x[(b * 1024 + c) * PP + h * NH + w];
    }
    float c[16][4], c2[16];
#pragma unroll
    for (int k = 0; k < 16; k++) {
#pragma unroll
        for (int j = 0; j < 4; j++) c[k][j] = cent[(cb * 16 + k) * 4 + j];
        float s = __fmul_rn(c[k][0], c[k][0]);
        s = __fadd_rn(s, __fmul_rn(c[k][1], c[k][1]));
        s = __fadd_rn(s, __fmul_rn(c[k][2], c[k][2]));
        s = __fadd_rn(s, __fmul_rn(c[k][3], c[k][3]));
        c2[k] = s;
    }
    __syncthreads();
    for (int w = 0; w < NH; w++) {
        const float v0 = xs[(cb * 4 + 0) * 14 + w];
        const float v1 = xs[(cb * 4 + 1) * 14 + w];
        const float v2 = xs[(cb * 4 + 2) * 14 + w];
        const float v3 = xs[(cb * 4 + 3) * 14 + w];
        float best = 3.4e38f; int bi = 0;
#pragma unroll
        for (int k = 0; k < 16; k++) {
            float d = __fmaf_rn(v0, c[k][0], 0.0f);
            d = __fmaf_rn(v1, c[k][1], d);
            d = __fmaf_rn(v2, c[k][2], d);
            d = __fmaf_rn(v3, c[k][3], d);
            const float s = __fadd_rn(c2[k], -__fmul_rn(2.0f, d));
            if (s < best) { best = s; bi = k; }
        }
        ((unsigned char*)g_idx1)[(b * PP + h * NH + w) * 256 + cb] = (unsigned char)bi;
    }
}

// ---------------- encode2 (unchanged, passing). smem 147456 ----------------
__global__ void __launch_bounds__(256) k_encode2(const float* __restrict__ cent) {
    extern __shared__ float sc[];
    const int b = blockIdx.y, h = blockIdx.x, c = threadIdx.x;
    for (int i = 0; i < 144; i++) sc[i * 256 + c] = cent[c * 144 + i];
    float c2[16];
#pragma unroll
    for (int k = 0; k < 16; k++) {
        float t0 = cent[c * 144 + k * 9];
        float s = __fmul_rn(t0, t0);
#pragma unroll
        for (int t = 1; t < 9; t++) {
            const float tv = cent[c * 144 + k * 9 + t];
            s = __fadd_rn(s, __fmul_rn(tv, tv));
        }
        c2[k] = s;
    }
    __syncthreads();
    for (int w = 0; w < NH; w++) {
        float v[9];
#pragma unroll
        for (int i = 0; i < 3; i++)
#pragma unroll
            for (int j = 0; j < 3; j++) {
                const int hh = h - 1 + i, ww = w - 1 + j;
                float val = 0.0f;
                if (hh >= 0 && hh < NH && ww >= 0 && ww < NH)
                    val = g_out1[(b * PP + hh * NH + ww) * 256 + c];
                v[i * 3 + j] = val;
            }
        float best = 3.4e38f; int bi = 0;
#pragma unroll
        for (int k = 0; k < 16; k++) {
            float d = __fmaf_rn(v[0], sc[(k * 9 + 0) * 256 + c], 0.0f);
#pragma unroll
            for (int t = 1; t < 9; t++) d = __fmaf_rn(v[t], sc[(k * 9 + t) * 256 + c], d);
            const float s = __fadd_rn(c2[k], -__fmul_rn(2.0f, d));
            if (s < best) { best = s; bi = k; }
        }
        ((unsigned char*)g_idx2)[(b * PP + h * NH + w) * 256 + c] = (unsigned char)bi;
    }
}

// ===================================================================
// accum12: kc=248 blocked fold, 512 threads = 64 og x 8 ps.
// Triple-buffered cp.async, ONE __syncthreads per chunk:
//   wait(own group n) -> barrier (visibility + WAR) -> prefetch n+2 -> compute n
// grid (4, 32). dyn smem = 3*65536 + 49*64*4 = 209152.
// ===================================================================
__device__ __forceinline__ void accum12_body(const unsigned int* __restrict__ gidx,
                                             const float* __restrict__ lut,
                                             const float* __restrict__ scale,
                                             const float* __restrict__ bias,
                                             float* __restrict__ out) {
    extern __shared__ float sm[];
    float* lutS = sm;                                       // 3 * 16384 floats
    unsigned int* idxS = (unsigned int*)(sm + 3 * 16384);   // 49*64 words
    const int b = blockIdx.y, q = blockIdx.x, t = threadIdx.x;
    const int og = t & 63, ps = t >> 6;            // ps in 0..7
    const int p0 = q * 49;
    const unsigned int* gi = gidx + (b * PP + p0) * 64;
    for (int i = t; i < 49 * 64; i += 512) idxS[i] = gi[i];
    const int NI = (ps == 0) ? 7 : 6;              // p = ps + 8*i < 49
    float4 acc[7], tot[7];
#pragma unroll
    for (int i = 0; i < 7; i++) {
        acc[i] = make_float4(0.f, 0.f, 0.f, 0.f);
        tot[i] = make_float4(0.f, 0.f, 0.f, 0.f);
    }
    const unsigned int sbase = (unsigned int)__cvta_generic_to_shared(lutS);
    const float4* gl = (const float4*)lut;
    // prologue: prefetch chunks 0 and 1 into buffers 0 and 1
#pragma unroll
    for (int i = 0; i < 8; i++) cp16(sbase + (t + i * 512) * 16, (const void*)(gl + t + i * 512));
    cpcommit();
#pragma unroll
    for (int i = 0; i < 8; i++) cp16(sbase + 65536u + (t + i * 512) * 16, (const void*)(gl + 4096 + t + i * 512));
    cpcommit();
    for (int ch = 0; ch < 64; ch++) {
        if (ch == 63) cpwait0(); else cpwait1();   // own copies of chunk ch done
        __syncthreads();                            // all copies visible; compute ch-1 done everywhere
        if (ch + 2 < 64) {                          // prefetch ch+2 into buffer consumed at ch-1
            const float4* s = gl + (ch + 2) * 4096;
            const unsigned int d0 = sbase + (unsigned int)((ch + 2) % 3) * 65536u;
#pragma unroll
            for (int i = 0; i < 8; i++) cp16(d0 + (t + i * 512) * 16, (const void*)(s + t + i * 512));
            cpcommit();
        }
        const float* L = lutS + (ch % 3) * 16384;
        int fB[4], fC[4], Tt[4], any = 0;
#pragma unroll
        for (int j = 0; j < 4; j++) {
            const int c = (ch << 2) + j, k16 = c << 4;
            fB[j] = ((k16 % 248) == 0 && c > 0) ? 1 : 0;
            const int pan0 = k16 / 248, pan1 = (k16 + 15) / 248;
            fC[j] = (!fB[j] && pan1 > pan0) ? 1 : 0;
            Tt[j] = pan1 * 248 - k16;
            any |= fB[j] | fC[j];
        }
        if (!any) {
#pragma unroll
            for (int i = 0; i < 7; i++) {
                if (i < NI) {
                    const unsigned int wv = idxS[(ps + 8 * i) * 64 + ch];
#pragma unroll
                    for (int j = 0; j < 4; j++) {
                        const unsigned int idx = (wv >> (8 * j)) & 255u;
                        const float4 lv = *(const float4*)(L + (((j << 4) + idx) << 8) + (og << 2));
                        acc[i].x = __fadd_rn(acc[i].x, lv.x);
                        acc[i].y = __fadd_rn(acc[i].y, lv.y);
                        acc[i].z = __fadd_rn(acc[i].z, lv.z);
                        acc[i].w = __fadd_rn(acc[i].w, lv.w);
                    }
                }
            }
        } else {
#pragma unroll
            for (int i = 0; i < 7; i++) {
                if (i < NI) {
                    const unsigned int wv = idxS[(ps + 8 * i) * 64 + ch];
#pragma unroll
                    for (int j = 0; j < 4; j++) {
                        const unsigned int idx = (wv >> (8 * j)) & 255u;
                        const float4 lv = *(const float4*)(L + (((j << 4) + idx) << 8) + (og << 2));
                        const bool foldB = fB[j] || (fC[j] && (int)idx >= Tt[j]);
                        if (foldB) {
                            tot[i].x = __fadd_rn(tot[i].x, acc[i].x); acc[i].x = lv.x;
                            tot[i].y = __fadd_rn(tot[i].y, acc[i].y); acc[i].y = lv.y;
                            tot[i].z = __fadd_rn(tot[i].z, acc[i].z); acc[i].z = lv.z;
                            tot[i].w = __fadd_rn(tot[i].w, acc[i].w); acc[i].w = lv.w;
                        } else {
                            acc[i].x = __fadd_rn(acc[i].x, lv.x);
                            acc[i].y = __fadd_rn(acc[i].y, lv.y);
                            acc[i].z = __fadd_rn(acc[i].z, lv.z);
                            acc[i].w = __fadd_rn(acc[i].w, lv.w);
                            if (fC[j]) {
                                tot[i].x = __fadd_rn(tot[i].x, acc[i].x); acc[i].x = 0.f;
                                tot[i].y = __fadd_rn(tot[i].y, acc[i].y); acc[i].y = 0.f;
                                tot[i].z = __fadd_rn(tot[i].z, acc[i].z); acc[i].z = 0.f;
                                tot[i].w = __fadd_rn(tot[i].w, acc[i].w); acc[i].w = 0.f;
                            }
                        }
                    }
                }
            }
        }
    }
    const float4 sc4 = ((const float4*)scale)[og];
    const float4 bi4 = ((const float4*)bias)[og];
#pragma unroll
    for (int i = 0; i < 7; i++) {
        if (i < NI) {
            const int p = p0 + ps + 8 * i;
            float4 r; float s;
            s = __fadd_rn(tot[i].x, acc[i].x); r.x = fmaxf(__fadd_rn(__fmul_rn(s, sc4.x), bi4.x), 0.0f);
            s = __fadd_rn(tot[i].y, acc[i].y); r.y = fmaxf(__fadd_rn(__fmul_rn(s, sc4.y), bi4.y), 0.0f);
            s = __fadd_rn(tot[i].z, acc[i].z); r.z = fmaxf(__fadd_rn(__fmul_rn(s, sc4.z), bi4.z), 0.0f);
            s = __fadd_rn(tot[i].w, acc[i].w); r.w = fmaxf(__fadd_rn(__fmul_rn(s, sc4.w), bi4.w), 0.0f);
            *(float4*)(out + (b * PP + p) * 256 + (og << 2)) = r;
        }
    }
}

__global__ void __launch_bounds__(512, 1) k_accum_l1(const float* __restrict__ lut,
                                                     const float* __restrict__ scale,
                                                     const float* __restrict__ bias) {
    accum12_body(g_idx1, lut, scale, bias, g_out1);
}
__global__ void __launch_bounds__(512, 1) k_accum_l2(const float* __restrict__ lut,
                                                     const float* __restrict__ scale,
                                                     const float* __restrict__ bias) {
    accum12_body(g_idx2, lut, scale, bias, g_out2);
}

// ---------------- encode3 (unchanged, passing) ----------------
__global__ void __launch_bounds__(64) k_encode3(const float* __restrict__ cent) {
    const int b = blockIdx.y, h = blockIdx.x, cb = threadIdx.x;
    float c[16][4], c2[16];
#pragma unroll
    for (int k = 0; k < 16; k++) {
#pragma unroll
        for (int j = 0; j < 4; j++) c[k][j] = cent[(cb * 16 + k) * 4 + j];
        float s = __fmul_rn(c[k][0], c[k][0]);
        s = __fadd_rn(s, __fmul_rn(c[k][1], c[k][1]));
        s = __fadd_rn(s, __fmul_rn(c[k][2], c[k][2]));
        s = __fadd_rn(s, __fmul_rn(c[k][3], c[k][3]));
        c2[k] = s;
    }
    for (int w = 0; w < NH; w++) {
        const int p = h * NH + w;
        const float4 v = *(const float4*)&g_out2[(b * PP + p) * 256 + cb * 4];
        float best = 3.4e38f; int bi = 0;
#pragma unroll
        for (int k = 0; k < 16; k++) {
            float d = __fmaf_rn(v.x, c[k][0], 0.0f);
            d = __fmaf_rn(v.y, c[k][1], d);
            d = __fmaf_rn(v.z, c[k][2], d);
            d = __fmaf_rn(v.w, c[k][3], d);
            const float s = __fadd_rn(c2[k], -__fmul_rn(2.0f, d));
            if (s < best) { best = s; bi = k; }
        }
        ((unsigned char*)g_idx3)[(b * PP + p) * 64 + cb] = (unsigned char)bi;
    }
}

// ===================================================================
// accum3: flat sum, 512 threads = 128 og x 4 ps, p = ps + 4*i.
// Triple-buffered, one barrier per chunk. Chunk = 2 cb (64 KB).
// grid (8, 32): pg = gx&3, oh = gx>>2.
// dyn smem = 3*65536 + 49*64 = 199744.
// ===================================================================
__global__ void __launch_bounds__(512, 1) k_accum3(const float* __restrict__ lut,
                                                   const float* __restrict__ scale,
                                                   const float* __restrict__ bias,
                                                   const float* __restrict__ xin,
                                                   float* __restrict__ out) {
    extern __shared__ float sm[];
    float* lutS = sm;                                        // 3 * 16384 floats
    unsigned char* idxB = (unsigned char*)(sm + 3 * 16384);  // 49*64 bytes
    const int b = blockIdx.y, gx = blockIdx.x, t = threadIdx.x;
    const int pg = gx & 3, oh = gx >> 2;
    const int og = t & 127, ps = t >> 7;           // ps in 0..3
    const int p0 = pg * 49;
    const unsigned int* gi = (const unsigned int*)((const unsigned char*)g_idx3 + (b * PP + p0) * 64);
    for (int i = t; i < 49 * 16; i += 512) ((unsigned int*)idxB)[i] = gi[i];
    const int NI = (ps == 0) ? 13 : 12;
    float4 acc[13];
#pragma unroll
    for (int i = 0; i < 13; i++) acc[i] = make_float4(0.f, 0.f, 0.f, 0.f);
    const unsigned int sbase = (unsigned int)__cvta_generic_to_shared(lutS);
    const float4* gl = (const float4*)lut;
    // prologue: chunks 0,1 into buffers 0,1 (chunk c2 = cb {2c2, 2c2+1}, o-half slice)
#pragma unroll
    for (int i = 0; i < 8; i++) {
        const int e4 = i * 512 + t;
        const int row = e4 >> 7, c4 = e4 & 127;
        cp16(sbase + e4 * 16, (const void*)(gl + row * 256 + oh * 128 + c4));
    }
    cpcommit();
#pragma unroll
    for (int i = 0; i < 8; i++) {
        const int e4 = i * 512 + t;
        const int row = e4 >> 7, c4 = e4 & 127;
        cp16(sbase + 65536u + e4 * 16, (const void*)(gl + (32 + row) * 256 + oh * 128 + c4));
    }
    cpcommit();
    for (int c2 = 0; c2 < 32; c2++) {
        if (c2 == 31) cpwait0(); else cpwait1();
        __syncthreads();
        if (c2 + 2 < 32) {
            const unsigned int d0 = sbase + (unsigned int)((c2 + 2) % 3) * 65536u;
#pragma unroll
            for (int i = 0; i < 8; i++) {
                const int e4 = i * 512 + t;
                const int row = e4 >> 7, c4 = e4 & 127;
                cp16(d0 + e4 * 16, (const void*)(gl + ((c2 + 2) * 32 + row) * 256 + oh * 128 + c4));
            }
            cpcommit();
        }
        const float* L = lutS + (c2 % 3) * 16384;
#pragma unroll
        for (int i = 0; i < 13; i++) {
            if (i < NI) {
                const int p = ps + 4 * i;
                const unsigned char* ib = idxB + p * 64 + (c2 << 1);
#pragma unroll
                for (int j = 0; j < 2; j++) {
                    const unsigned int idx = ib[j];
                    const float4 lv = *(const float4*)(L + (((j << 4) + idx) << 9) + (og << 2));
                    acc[i].x = __fadd_rn(acc[i].x, lv.x);
                    acc[i].y = __fadd_rn(acc[i].y, lv.y);
                    acc[i].z = __fadd_rn(acc[i].z, lv.z);
                    acc[i].w = __fadd_rn(acc[i].w, lv.w);
                }
            }
        }
    }
    float* tr = lutS;   // 512*49 floats = 100352 B, fits
    __syncthreads();
#pragma unroll
    for (int i = 0; i < 13; i++) {
        if (i < NI) {
            const int p = ps + 4 * i;
            tr[(og * 4 + 0) * 49 + p] = acc[i].x;
            tr[(og * 4 + 1) * 49 + p] = acc[i].y;
            tr[(og * 4 + 2) * 49 + p] = acc[i].z;
            tr[(og * 4 + 3) * 49 + p] = acc[i].w;
        }
    }
    __syncthreads();
    {
        const int ol = t;
        const int O = oh * 512 + ol;
        const float scv = scale[O], biv = bias[O];
        const int base = (b * 1024 + O) * PP + p0;
        const float* trr = tr + ol * 49;
        for (int p = 0; p < 49; p++) {
            float r = __fadd_rn(__fadd_rn(__fmul_rn(trr[p], scv), biv), xin[base + p]);
            out[base + p] = fmaxf(r, 0.0f);
        }
    }
}

extern "C" void kernel_launch(void* const* d_in, const int* in_sizes, int n_in,
                              void* d_out, int out_size) {
    const float* x   = (const float*)d_in[0];
    const float* c1c = (const float*)d_in[1];
    const float* c1l = (const float*)d_in[2];
    const float* c1s = (const float*)d_in[3];
    const float* c1b = (const float*)d_in[4];
    const float* c2c = (const float*)d_in[5];
    const float* c2l = (const float*)d_in[6];
    const float* c2s = (const float*)d_in[7];
    const float* c2b = (const float*)d_in[8];
    const float* c3c = (const float*)d_in[9];
    const float* c3l = (const float*)d_in[10];
    const float* c3s = (const float*)d_in[11];
    const float* c3b = (const float*)d_in[12];
    float* out = (float*)d_out;

    cudaFuncSetAttribute(k_encode1,  cudaFuncAttributeMaxDynamicSharedMemorySize, 57344);
    cudaFuncSetAttribute(k_encode2,  cudaFuncAttributeMaxDynamicSharedMemorySize, 147456);
    cudaFuncSetAttribute(k_accum_l1, cudaFuncAttributeMaxDynamicSharedMemorySize, 209152);
    cudaFuncSetAttribute(k_accum_l2, cudaFuncAttributeMaxDynamicSharedMemorySize, 209152);
    cudaFuncSetAttribute(k_accum3,   cudaFuncAttributeMaxDynamicSharedMemorySize, 199744);

    k_encode1<<<dim3(NH, BB), 256, 57344>>>(x, c1c);
    k_accum_l1<<<dim3(4, BB), 512, 209152>>>(c1l, c1s, c1b);
    k_encode2<<<dim3(NH, BB), 256, 147456>>>(c2c);
    k_accum_l2<<<dim3(4, BB), 512, 209152>>>(c2l, c2s, c2b);
    k_encode3<<<dim3(NH, BB), 64>>>(c3c);
    k_accum3<<<dim3(8, BB), 512, 199744>>>(c3l, c3s, c3b, x, out);
    (void)in_sizes; (void)n_in; (void)out_size;
}

// round 14
// speedup vs baseline: 1.2311x; 1.2311x over previous
#include <cuda_runtime.h>

#define BB 32
#define PP 196
#define NH 14

static __device__ unsigned int g_idx1[BB * PP * 64];
static __device__ float        g_out1[BB * PP * 256];
static __device__ unsigned int g_idx2[BB * PP * 64];
static __device__ float        g_out2[BB * PP * 256];
static __device__ unsigned int g_idx3[BB * PP * 16];

__device__ __forceinline__ void cp16(unsigned int dst, const void* src) {
    asm volatile("cp.async.cg.shared.global [%0], [%1], 16;\n" :: "r"(dst), "l"(src));
}
__device__ __forceinline__ void cpcommit() { asm volatile("cp.async.commit_group;\n" ::: "memory"); }
__device__ __forceinline__ void cpwait0()  { asm volatile("cp.async.wait_group 0;\n" ::: "memory"); }
__device__ __forceinline__ void cpwait1()  { asm volatile("cp.async.wait_group 1;\n" ::: "memory"); }

// ---------------- encode1: smem-staged x tile, FMA dots. dyn smem 57344 ----------------
__global__ void __launch_bounds__(256) k_encode1(const float* __restrict__ x,
                                                 const float* __restrict__ cent) {
    extern __shared__ float xs[];   // [c][w]: 1024*14 floats
    const int b = blockIdx.y, h = blockIdx.x, cb = threadIdx.x;
    for (int i = cb; i < 1024 * 14; i += 256) {
        const int c = i / 14, w = i % 14;
        xs[i] = x[(b * 1024 + c) * PP + h * NH + w];
    }
    float c[16][4], c2[16];
#pragma unroll
    for (int k = 0; k < 16; k++) {
#pragma unroll
        for (int j = 0; j < 4; j++) c[k][j] = cent[(cb * 16 + k) * 4 + j];
        float s = __fmul_rn(c[k][0], c[k][0]);
        s = __fadd_rn(s, __fmul_rn(c[k][1], c[k][1]));
        s = __fadd_rn(s, __fmul_rn(c[k][2], c[k][2]));
        s = __fadd_rn(s, __fmul_rn(c[k][3], c[k][3]));
        c2[k] = s;
    }
    __syncthreads();
    for (int w = 0; w < NH; w++) {
        const float v0 = xs[(cb * 4 + 0) * 14 + w];
        const float v1 = xs[(cb * 4 + 1) * 14 + w];
        const float v2 = xs[(cb * 4 + 2) * 14 + w];
        const float v3 = xs[(cb * 4 + 3) * 14 + w];
        float best = 3.4e38f; int bi = 0;
#pragma unroll
        for (int k = 0; k < 16; k++) {
            float d = __fmaf_rn(v0, c[k][0], 0.0f);
            d = __fmaf_rn(v1, c[k][1], d);
            d = __fmaf_rn(v2, c[k][2], d);
            d = __fmaf_rn(v3, c[k][3], d);
            const float s = __fadd_rn(c2[k], -__fmul_rn(2.0f, d));
            if (s < best) { best = s; bi = k; }
        }
        ((unsigned char*)g_idx1)[(b * PP + h * NH + w) * 256 + cb] = (unsigned char)bi;
    }
}

// ---------------- encode2 (unchanged, passing). smem 147456 ----------------
__global__ void __launch_bounds__(256) k_encode2(const float* __restrict__ cent) {
    extern __shared__ float sc[];
    const int b = blockIdx.y, h = blockIdx.x, c = threadIdx.x;
    for (int i = 0; i < 144; i++) sc[i * 256 + c] = cent[c * 144 + i];
    float c2[16];
#pragma unroll
    for (int k = 0; k < 16; k++) {
        float t0 = cent[c * 144 + k * 9];
        float s = __fmul_rn(t0, t0);
#pragma unroll
        for (int t = 1; t < 9; t++) {
            const float tv = cent[c * 144 + k * 9 + t];
            s = __fadd_rn(s, __fmul_rn(tv, tv));
        }
        c2[k] = s;
    }
    __syncthreads();
    for (int w = 0; w < NH; w++) {
        float v[9];
#pragma unroll
        for (int i = 0; i < 3; i++)
#pragma unroll
            for (int j = 0; j < 3; j++) {
                const int hh = h - 1 + i, ww = w - 1 + j;
                float val = 0.0f;
                if (hh >= 0 && hh < NH && ww >= 0 && ww < NH)
                    val = g_out1[(b * PP + hh * NH + ww) * 256 + c];
                v[i * 3 + j] = val;
            }
        float best = 3.4e38f; int bi = 0;
#pragma unroll
        for (int k = 0; k < 16; k++) {
            float d = __fmaf_rn(v[0], sc[(k * 9 + 0) * 256 + c], 0.0f);
#pragma unroll
            for (int t = 1; t < 9; t++) d = __fmaf_rn(v[t], sc[(k * 9 + t) * 256 + c], d);
            const float s = __fadd_rn(c2[k], -__fmul_rn(2.0f, d));
            if (s < best) { best = s; bi = k; }
        }
        ((unsigned char*)g_idx2)[(b * PP + h * NH + w) * 256 + c] = (unsigned char)bi;
    }
}

// ===================================================================
// accum12 (EXACT R11 best): kc=248 blocked fold, 512 threads = 64 og x 8 ps.
// Double-buffered cp.async. grid (4, 32). dyn smem = 2*65536 + 49*64*4 = 143616.
// ===================================================================
__device__ __forceinline__ void accum12_body(const unsigned int* __restrict__ gidx,
                                             const float* __restrict__ lut,
                                             const float* __restrict__ scale,
                                             const float* __restrict__ bias,
                                             float* __restrict__ out) {
    extern __shared__ float sm[];
    float* lutS = sm;
    unsigned int* idxS = (unsigned int*)(sm + 2 * 16384);
    const int b = blockIdx.y, q = blockIdx.x, t = threadIdx.x;
    const int og = t & 63, ps = t >> 6;
    const int p0 = q * 49;
    const unsigned int* gi = gidx + (b * PP + p0) * 64;
    for (int i = t; i < 49 * 64; i += 512) idxS[i] = gi[i];
    const int NI = (ps == 0) ? 7 : 6;
    float4 acc[7], tot[7];
#pragma unroll
    for (int i = 0; i < 7; i++) {
        acc[i] = make_float4(0.f, 0.f, 0.f, 0.f);
        tot[i] = make_float4(0.f, 0.f, 0.f, 0.f);
    }
    const unsigned int sbase = (unsigned int)__cvta_generic_to_shared(lutS);
    const float4* gl = (const float4*)lut;
#pragma unroll
    for (int i = 0; i < 8; i++) cp16(sbase + (t + i * 512) * 16, (const void*)(gl + t + i * 512));
    cpcommit();
    int buf = 0;
    for (int ch = 0; ch < 64; ch++) {
        if (ch + 1 < 64) {
            const float4* s = gl + (ch + 1) * 4096;
            const unsigned int d0 = sbase + (unsigned int)(buf ^ 1) * 65536u;
#pragma unroll
            for (int i = 0; i < 8; i++) cp16(d0 + (t + i * 512) * 16, (const void*)(s + t + i * 512));
            cpcommit();
            cpwait1();
        } else {
            cpwait0();
        }
        __syncthreads();
        const float* L = lutS + buf * 16384;
        int fB[4], fC[4], Tt[4], any = 0;
#pragma unroll
        for (int j = 0; j < 4; j++) {
            const int c = (ch << 2) + j, k16 = c << 4;
            fB[j] = ((k16 % 248) == 0 && c > 0) ? 1 : 0;
            const int pan0 = k16 / 248, pan1 = (k16 + 15) / 248;
            fC[j] = (!fB[j] && pan1 > pan0) ? 1 : 0;
            Tt[j] = pan1 * 248 - k16;
            any |= fB[j] | fC[j];
        }
        if (!any) {
#pragma unroll
            for (int i = 0; i < 7; i++) {
                if (i < NI) {
                    const unsigned int wv = idxS[(ps + 8 * i) * 64 + ch];
#pragma unroll
                    for (int j = 0; j < 4; j++) {
                        const unsigned int idx = (wv >> (8 * j)) & 255u;
                        const float4 lv = *(const float4*)(L + (((j << 4) + idx) << 8) + (og << 2));
                        acc[i].x = __fadd_rn(acc[i].x, lv.x);
                        acc[i].y = __fadd_rn(acc[i].y, lv.y);
                        acc[i].z = __fadd_rn(acc[i].z, lv.z);
                        acc[i].w = __fadd_rn(acc[i].w, lv.w);
                    }
                }
            }
        } else {
#pragma unroll
            for (int i = 0; i < 7; i++) {
                if (i < NI) {
                    const unsigned int wv = idxS[(ps + 8 * i) * 64 + ch];
#pragma unroll
                    for (int j = 0; j < 4; j++) {
                        const unsigned int idx = (wv >> (8 * j)) & 255u;
                        const float4 lv = *(const float4*)(L + (((j << 4) + idx) << 8) + (og << 2));
                        const bool foldB = fB[j] || (fC[j] && (int)idx >= Tt[j]);
                        if (foldB) {
                            tot[i].x = __fadd_rn(tot[i].x, acc[i].x); acc[i].x = lv.x;
                            tot[i].y = __fadd_rn(tot[i].y, acc[i].y); acc[i].y = lv.y;
                            tot[i].z = __fadd_rn(tot[i].z, acc[i].z); acc[i].z = lv.z;
                            tot[i].w = __fadd_rn(tot[i].w, acc[i].w); acc[i].w = lv.w;
                        } else {
                            acc[i].x = __fadd_rn(acc[i].x, lv.x);
                            acc[i].y = __fadd_rn(acc[i].y, lv.y);
                            acc[i].z = __fadd_rn(acc[i].z, lv.z);
                            acc[i].w = __fadd_rn(acc[i].w, lv.w);
                            if (fC[j]) {
                                tot[i].x = __fadd_rn(tot[i].x, acc[i].x); acc[i].x = 0.f;
                                tot[i].y = __fadd_rn(tot[i].y, acc[i].y); acc[i].y = 0.f;
                                tot[i].z = __fadd_rn(tot[i].z, acc[i].z); acc[i].z = 0.f;
                                tot[i].w = __fadd_rn(tot[i].w, acc[i].w); acc[i].w = 0.f;
                            }
                        }
                    }
                }
            }
        }
        __syncthreads();
        buf ^= 1;
    }
    const float4 sc4 = ((const float4*)scale)[og];
    const float4 bi4 = ((const float4*)bias)[og];
#pragma unroll
    for (int i = 0; i < 7; i++) {
        if (i < NI) {
            const int p = p0 + ps + 8 * i;
            float4 r; float s;
            s = __fadd_rn(tot[i].x, acc[i].x); r.x = fmaxf(__fadd_rn(__fmul_rn(s, sc4.x), bi4.x), 0.0f);
            s = __fadd_rn(tot[i].y, acc[i].y); r.y = fmaxf(__fadd_rn(__fmul_rn(s, sc4.y), bi4.y), 0.0f);
            s = __fadd_rn(tot[i].z, acc[i].z); r.z = fmaxf(__fadd_rn(__fmul_rn(s, sc4.z), bi4.z), 0.0f);
            s = __fadd_rn(tot[i].w, acc[i].w); r.w = fmaxf(__fadd_rn(__fmul_rn(s, sc4.w), bi4.w), 0.0f);
            *(float4*)(out + (b * PP + p) * 256 + (og << 2)) = r;
        }
    }
}

__global__ void __launch_bounds__(512, 1) k_accum_l1(const float* __restrict__ lut,
                                                     const float* __restrict__ scale,
                                                     const float* __restrict__ bias) {
    accum12_body(g_idx1, lut, scale, bias, g_out1);
}
__global__ void __launch_bounds__(512, 1) k_accum_l2(const float* __restrict__ lut,
                                                     const float* __restrict__ scale,
                                                     const float* __restrict__ bias) {
    accum12_body(g_idx2, lut, scale, bias, g_out2);
}

// ---------------- encode3 (unchanged, passing) ----------------
__global__ void __launch_bounds__(64) k_encode3(const float* __restrict__ cent) {
    const int b = blockIdx.y, h = blockIdx.x, cb = threadIdx.x;
    float c[16][4], c2[16];
#pragma unroll
    for (int k = 0; k < 16; k++) {
#pragma unroll
        for (int j = 0; j < 4; j++) c[k][j] = cent[(cb * 16 + k) * 4 + j];
        float s = __fmul_rn(c[k][0], c[k][0]);
        s = __fadd_rn(s, __fmul_rn(c[k][1], c[k][1]));
        s = __fadd_rn(s, __fmul_rn(c[k][2], c[k][2]));
        s = __fadd_rn(s, __fmul_rn(c[k][3], c[k][3]));
        c2[k] = s;
    }
    for (int w = 0; w < NH; w++) {
        const int p = h * NH + w;
        const float4 v = *(const float4*)&g_out2[(b * PP + p) * 256 + cb * 4];
        float best = 3.4e38f; int bi = 0;
#pragma unroll
        for (int k = 0; k < 16; k++) {
            float d = __fmaf_rn(v.x, c[k][0], 0.0f);
            d = __fmaf_rn(v.y, c[k][1], d);
            d = __fmaf_rn(v.z, c[k][2], d);
            d = __fmaf_rn(v.w, c[k][3], d);
            const float s = __fadd_rn(c2[k], -__fmul_rn(2.0f, d));
            if (s < best) { best = s; bi = k; }
        }
        ((unsigned char*)g_idx3)[(b * PP + p) * 64 + cb] = (unsigned char)bi;
    }
}

// ===================================================================
// accum3: flat sum over 64 cb, BN + residual + relu.
// FLAT grid of 296 blocks = 148 position-tiles x 2 o-halves (2 even waves).
// tile = gx>>1, oh = gx&1. Tile covers flat positions [start, start+cnt),
// cnt = 43 (tile<56) or 42. 512 threads = 128 og x 4 ps; p_local = ps + 4*i.
// Double-buffered 2-cb chunks (64 KB). dyn smem = 2*65536 + 43*64 = 133888.
// Transpose epilogue stride 45 (odd, conflict-free). Sum order unchanged.
// ===================================================================
__global__ void __launch_bounds__(512, 1) k_accum3(const float* __restrict__ lut,
                                                   const float* __restrict__ scale,
                                                   const float* __restrict__ bias,
                                                   const float* __restrict__ xin,
                                                   float* __restrict__ out) {
    extern __shared__ float sm[];
    float* lutS = sm;                                        // 2 * 16384 floats
    unsigned char* idxB = (unsigned char*)(sm + 2 * 16384);  // up to 43*64 bytes
    const int gx = blockIdx.x, t = threadIdx.x;
    const int tile = gx >> 1, oh = gx & 1;
    const int cnt = (tile < 56) ? 43 : 42;
    const int start = (tile < 56) ? tile * 43 : 56 * 43 + (tile - 56) * 42;  // flat position
    const int og = t & 127, ps = t >> 7;           // ps in 0..3
    const unsigned int* gi = (const unsigned int*)((const unsigned char*)g_idx3 + start * 64);
    for (int i = t; i < cnt * 16; i += 512) ((unsigned int*)idxB)[i] = gi[i];
    float4 acc[11];
#pragma unroll
    for (int i = 0; i < 11; i++) acc[i] = make_float4(0.f, 0.f, 0.f, 0.f);
    const unsigned int sbase = (unsigned int)__cvta_generic_to_shared(lutS);
    const float4* gl = (const float4*)lut;
#pragma unroll
    for (int i = 0; i < 8; i++) {
        const int e4 = i * 512 + t;
        const int row = e4 >> 7, c4 = e4 & 127;
        cp16(sbase + e4 * 16, (const void*)(gl + row * 256 + oh * 128 + c4));
    }
    cpcommit();
    int buf = 0;
    for (int c2 = 0; c2 < 32; c2++) {
        if (c2 + 1 < 32) {
            const unsigned int d0 = sbase + (unsigned int)(buf ^ 1) * 65536u;
#pragma unroll
            for (int i = 0; i < 8; i++) {
                const int e4 = i * 512 + t;
                const int row = e4 >> 7, c4 = e4 & 127;
                cp16(d0 + e4 * 16, (const void*)(gl + ((c2 + 1) * 32 + row) * 256 + oh * 128 + c4));
            }
            cpcommit();
            cpwait1();
        } else {
            cpwait0();
        }
        __syncthreads();
        const float* L = lutS + buf * 16384;
#pragma unroll
        for (int i = 0; i < 11; i++) {
            const int p = ps + 4 * i;
            if (p < cnt) {
                const unsigned char* ib = idxB + p * 64 + (c2 << 1);
#pragma unroll
                for (int j = 0; j < 2; j++) {
                    const unsigned int idx = ib[j];
                    const float4 lv = *(const float4*)(L + (((j << 4) + idx) << 9) + (og << 2));
                    acc[i].x = __fadd_rn(acc[i].x, lv.x);
                    acc[i].y = __fadd_rn(acc[i].y, lv.y);
                    acc[i].z = __fadd_rn(acc[i].z, lv.z);
                    acc[i].w = __fadd_rn(acc[i].w, lv.w);
                }
            }
        }
        __syncthreads();
        buf ^= 1;
    }
    // transpose via smem: tr[o_local][p], stride 45 (512*45*4 = 92160 B fits)
    float* tr = lutS;
    __syncthreads();
#pragma unroll
    for (int i = 0; i < 11; i++) {
        const int p = ps + 4 * i;
        if (p < cnt) {
            tr[(og * 4 + 0) * 45 + p] = acc[i].x;
            tr[(og * 4 + 1) * 45 + p] = acc[i].y;
            tr[(og * 4 + 2) * 45 + p] = acc[i].z;
            tr[(og * 4 + 3) * 45 + p] = acc[i].w;
        }
    }
    __syncthreads();
    {
        const int ol = t;
        if (ol < 512) {
            const int O = oh * 512 + ol;
            const float scv = scale[O], biv = bias[O];
            const float* trr = tr + ol * 45;
            for (int p = 0; p < cnt; p++) {
                const int P = start + p;
                const int bb = P / 196, pp = P % 196;
                const int addr = (bb * 1024 + O) * PP + pp;
                float r = __fadd_rn(__fadd_rn(__fmul_rn(trr[p], scv), biv), xin[addr]);
                out[addr] = fmaxf(r, 0.0f);
            }
        }
    }
}

extern "C" void kernel_launch(void* const* d_in, const int* in_sizes, int n_in,
                              void* d_out, int out_size) {
    const float* x   = (const float*)d_in[0];
    const float* c1c = (const float*)d_in[1];
    const float* c1l = (const float*)d_in[2];
    const float* c1s = (const float*)d_in[3];
    const float* c1b = (const float*)d_in[4];
    const float* c2c = (const float*)d_in[5];
    const float* c2l = (const float*)d_in[6];
    const float* c2s = (const float*)d_in[7];
    const float* c2b = (const float*)d_in[8];
    const float* c3c = (const float*)d_in[9];
    const float* c3l = (const float*)d_in[10];
    const float* c3s = (const float*)d_in[11];
    const float* c3b = (const float*)d_in[12];
    float* out = (float*)d_out;

    cudaFuncSetAttribute(k_encode1,  cudaFuncAttributeMaxDynamicSharedMemorySize, 57344);
    cudaFuncSetAttribute(k_encode2,  cudaFuncAttributeMaxDynamicSharedMemorySize, 147456);
    cudaFuncSetAttribute(k_accum_l1, cudaFuncAttributeMaxDynamicSharedMemorySize, 143616);
    cudaFuncSetAttribute(k_accum_l2, cudaFuncAttributeMaxDynamicSharedMemorySize, 143616);
    cudaFuncSetAttribute(k_accum3,   cudaFuncAttributeMaxDynamicSharedMemorySize, 133888);

    k_encode1<<<dim3(NH, BB), 256, 57344>>>(x, c1c);
    k_accum_l1<<<dim3(4, BB), 512, 143616>>>(c1l, c1s, c1b);
    k_encode2<<<dim3(NH, BB), 256, 147456>>>(c2c);
    k_accum_l2<<<dim3(4, BB), 512, 143616>>>(c2l, c2s, c2b);
    k_encode3<<<dim3(NH, BB), 64>>>(c3c);
    k_accum3<<<dim3(296), 512, 133888>>>(c3l, c3s, c3b, x, out);
    (void)in_sizes; (void)n_in; (void)out_size;
}

// round 15
// speedup vs baseline: 1.2634x; 1.0263x over previous
#include <cuda_runtime.h>

#define BB 32
#define PP 196
#define NH 14

static __device__ unsigned int g_idx1[BB * PP * 64];
static __device__ float        g_out1[BB * PP * 256];
static __device__ unsigned int g_idx2[BB * PP * 64];
static __device__ float        g_out2[BB * PP * 256];
static __device__ unsigned int g_idx3[BB * PP * 16];

__device__ __forceinline__ void cp16(unsigned int dst, const void* src) {
    asm volatile("cp.async.cg.shared.global [%0], [%1], 16;\n" :: "r"(dst), "l"(src));
}
__device__ __forceinline__ void cpcommit() { asm volatile("cp.async.commit_group;\n" ::: "memory"); }
__device__ __forceinline__ void cpwait0()  { asm volatile("cp.async.wait_group 0;\n" ::: "memory"); }
__device__ __forceinline__ void cpwait1()  { asm volatile("cp.async.wait_group 1;\n" ::: "memory"); }

// ---------------- encode1: smem-staged x tile, FMA dots. dyn smem 57344 ----------------
__global__ void __launch_bounds__(256) k_encode1(const float* __restrict__ x,
                                                 const float* __restrict__ cent) {
    extern __shared__ float xs[];   // [c][w]: 1024*14 floats
    const int b = blockIdx.y, h = blockIdx.x, cb = threadIdx.x;
    for (int i = cb; i < 1024 * 14; i += 256) {
        const int c = i / 14, w = i % 14;
        xs[i] = x[(b * 1024 + c) * PP + h * NH + w];
    }
    float c[16][4], c2[16];
#pragma unroll
    for (int k = 0; k < 16; k++) {
#pragma unroll
        for (int j = 0; j < 4; j++) c[k][j] = cent[(cb * 16 + k) * 4 + j];
        float s = __fmul_rn(c[k][0], c[k][0]);
        s = __fadd_rn(s, __fmul_rn(c[k][1], c[k][1]));
        s = __fadd_rn(s, __fmul_rn(c[k][2], c[k][2]));
        s = __fadd_rn(s, __fmul_rn(c[k][3], c[k][3]));
        c2[k] = s;
    }
    __syncthreads();
    for (int w = 0; w < NH; w++) {
        const float v0 = xs[(cb * 4 + 0) * 14 + w];
        const float v1 = xs[(cb * 4 + 1) * 14 + w];
        const float v2 = xs[(cb * 4 + 2) * 14 + w];
        const float v3 = xs[(cb * 4 + 3) * 14 + w];
        float best = 3.4e38f; int bi = 0;
#pragma unroll
        for (int k = 0; k < 16; k++) {
            float d = __fmaf_rn(v0, c[k][0], 0.0f);
            d = __fmaf_rn(v1, c[k][1], d);
            d = __fmaf_rn(v2, c[k][2], d);
            d = __fmaf_rn(v3, c[k][3], d);
            const float s = __fadd_rn(c2[k], -__fmul_rn(2.0f, d));
            if (s < best) { best = s; bi = k; }
        }
        ((unsigned char*)g_idx1)[(b * PP + h * NH + w) * 256 + cb] = (unsigned char)bi;
    }
}

// ---------------- encode2 (unchanged, passing). smem 147456 ----------------
__global__ void __launch_bounds__(256) k_encode2(const float* __restrict__ cent) {
    extern __shared__ float sc[];
    const int b = blockIdx.y, h = blockIdx.x, c = threadIdx.x;
    for (int i = 0; i < 144; i++) sc[i * 256 + c] = cent[c * 144 + i];
    float c2[16];
#pragma unroll
    for (int k = 0; k < 16; k++) {
        float t0 = cent[c * 144 + k * 9];
        float s = __fmul_rn(t0, t0);
#pragma unroll
        for (int t = 1; t < 9; t++) {
            const float tv = cent[c * 144 + k * 9 + t];
            s = __fadd_rn(s, __fmul_rn(tv, tv));
        }
        c2[k] = s;
    }
    __syncthreads();
    for (int w = 0; w < NH; w++) {
        float v[9];
#pragma unroll
        for (int i = 0; i < 3; i++)
#pragma unroll
            for (int j = 0; j < 3; j++) {
                const int hh = h - 1 + i, ww = w - 1 + j;
                float val = 0.0f;
                if (hh >= 0 && hh < NH && ww >= 0 && ww < NH)
                    val = g_out1[(b * PP + hh * NH + ww) * 256 + c];
                v[i * 3 + j] = val;
            }
        float best = 3.4e38f; int bi = 0;
#pragma unroll
        for (int k = 0; k < 16; k++) {
            float d = __fmaf_rn(v[0], sc[(k * 9 + 0) * 256 + c], 0.0f);
#pragma unroll
            for (int t = 1; t < 9; t++) d = __fmaf_rn(v[t], sc[(k * 9 + t) * 256 + c], d);
            const float s = __fadd_rn(c2[k], -__fmul_rn(2.0f, d));
            if (s < best) { best = s; bi = k; }
        }
        ((unsigned char*)g_idx2)[(b * PP + h * NH + w) * 256 + c] = (unsigned char)bi;
    }
}

// ===================================================================
// accum12: kc=248 blocked fold. FLAT grid of 148 blocks (one full wave):
// tile gx covers flat positions [start, start+cnt), cnt = 43 (gx<56) or 42.
// 512 threads = 64 og x 8 ps; p_local = ps + 8*i (i<6, guarded p<cnt).
// Double-buffered cp.async. dyn smem = 2*65536 + 43*64*4 = 142080.
// ===================================================================
__device__ __forceinline__ void accum12_body(const unsigned int* __restrict__ gidx,
                                             const float* __restrict__ lut,
                                             const float* __restrict__ scale,
                                             const float* __restrict__ bias,
                                             float* __restrict__ out) {
    extern __shared__ float sm[];
    float* lutS = sm;
    unsigned int* idxS = (unsigned int*)(sm + 2 * 16384);   // up to 43*64 words
    const int gx = blockIdx.x, t = threadIdx.x;
    const int og = t & 63, ps = t >> 6;            // ps in 0..7
    const int cnt = (gx < 56) ? 43 : 42;
    const int start = (gx < 56) ? gx * 43 : 56 * 43 + (gx - 56) * 42;  // flat (b,p)
    const unsigned int* gi = gidx + start * 64;
    for (int i = t; i < cnt * 64; i += 512) idxS[i] = gi[i];
    float4 acc[6], tot[6];
#pragma unroll
    for (int i = 0; i < 6; i++) {
        acc[i] = make_float4(0.f, 0.f, 0.f, 0.f);
        tot[i] = make_float4(0.f, 0.f, 0.f, 0.f);
    }
    const unsigned int sbase = (unsigned int)__cvta_generic_to_shared(lutS);
    const float4* gl = (const float4*)lut;
#pragma unroll
    for (int i = 0; i < 8; i++) cp16(sbase + (t + i * 512) * 16, (const void*)(gl + t + i * 512));
    cpcommit();
    int buf = 0;
    for (int ch = 0; ch < 64; ch++) {
        if (ch + 1 < 64) {
            const float4* s = gl + (ch + 1) * 4096;
            const unsigned int d0 = sbase + (unsigned int)(buf ^ 1) * 65536u;
#pragma unroll
            for (int i = 0; i < 8; i++) cp16(d0 + (t + i * 512) * 16, (const void*)(s + t + i * 512));
            cpcommit();
            cpwait1();
        } else {
            cpwait0();
        }
        __syncthreads();
        const float* L = lutS + buf * 16384;
        int fB[4], fC[4], Tt[4], any = 0;
#pragma unroll
        for (int j = 0; j < 4; j++) {
            const int c = (ch << 2) + j, k16 = c << 4;
            fB[j] = ((k16 % 248) == 0 && c > 0) ? 1 : 0;
            const int pan0 = k16 / 248, pan1 = (k16 + 15) / 248;
            fC[j] = (!fB[j] && pan1 > pan0) ? 1 : 0;
            Tt[j] = pan1 * 248 - k16;
            any |= fB[j] | fC[j];
        }
        if (!any) {
#pragma unroll
            for (int i = 0; i < 6; i++) {
                const int p = ps + 8 * i;
                if (p < cnt) {
                    const unsigned int wv = idxS[p * 64 + ch];
#pragma unroll
                    for (int j = 0; j < 4; j++) {
                        const unsigned int idx = (wv >> (8 * j)) & 255u;
                        const float4 lv = *(const float4*)(L + (((j << 4) + idx) << 8) + (og << 2));
                        acc[i].x = __fadd_rn(acc[i].x, lv.x);
                        acc[i].y = __fadd_rn(acc[i].y, lv.y);
                        acc[i].z = __fadd_rn(acc[i].z, lv.z);
                        acc[i].w = __fadd_rn(acc[i].w, lv.w);
                    }
                }
            }
        } else {
#pragma unroll
            for (int i = 0; i < 6; i++) {
                const int p = ps + 8 * i;
                if (p < cnt) {
                    const unsigned int wv = idxS[p * 64 + ch];
#pragma unroll
                    for (int j = 0; j < 4; j++) {
                        const unsigned int idx = (wv >> (8 * j)) & 255u;
                        const float4 lv = *(const float4*)(L + (((j << 4) + idx) << 8) + (og << 2));
                        const bool foldB = fB[j] || (fC[j] && (int)idx >= Tt[j]);
                        if (foldB) {
                            tot[i].x = __fadd_rn(tot[i].x, acc[i].x); acc[i].x = lv.x;
                            tot[i].y = __fadd_rn(tot[i].y, acc[i].y); acc[i].y = lv.y;
                            tot[i].z = __fadd_rn(tot[i].z, acc[i].z); acc[i].z = lv.z;
                            tot[i].w = __fadd_rn(tot[i].w, acc[i].w); acc[i].w = lv.w;
                        } else {
                            acc[i].x = __fadd_rn(acc[i].x, lv.x);
                            acc[i].y = __fadd_rn(acc[i].y, lv.y);
                            acc[i].z = __fadd_rn(acc[i].z, lv.z);
                            acc[i].w = __fadd_rn(acc[i].w, lv.w);
                            if (fC[j]) {
                                tot[i].x = __fadd_rn(tot[i].x, acc[i].x); acc[i].x = 0.f;
                                tot[i].y = __fadd_rn(tot[i].y, acc[i].y); acc[i].y = 0.f;
                                tot[i].z = __fadd_rn(tot[i].z, acc[i].z); acc[i].z = 0.f;
                                tot[i].w = __fadd_rn(tot[i].w, acc[i].w); acc[i].w = 0.f;
                            }
                        }
                    }
                }
            }
        }
        __syncthreads();
        buf ^= 1;
    }
    const float4 sc4 = ((const float4*)scale)[og];
    const float4 bi4 = ((const float4*)bias)[og];
#pragma unroll
    for (int i = 0; i < 6; i++) {
        const int p = ps + 8 * i;
        if (p < cnt) {
            float4 r; float s;
            s = __fadd_rn(tot[i].x, acc[i].x); r.x = fmaxf(__fadd_rn(__fmul_rn(s, sc4.x), bi4.x), 0.0f);
            s = __fadd_rn(tot[i].y, acc[i].y); r.y = fmaxf(__fadd_rn(__fmul_rn(s, sc4.y), bi4.y), 0.0f);
            s = __fadd_rn(tot[i].z, acc[i].z); r.z = fmaxf(__fadd_rn(__fmul_rn(s, sc4.z), bi4.z), 0.0f);
            s = __fadd_rn(tot[i].w, acc[i].w); r.w = fmaxf(__fadd_rn(__fmul_rn(s, sc4.w), bi4.w), 0.0f);
            *(float4*)(out + (start + p) * 256 + (og << 2)) = r;
        }
    }
}

__global__ void __launch_bounds__(512, 1) k_accum_l1(const float* __restrict__ lut,
                                                     const float* __restrict__ scale,
                                                     const float* __restrict__ bias) {
    accum12_body(g_idx1, lut, scale, bias, g_out1);
}
__global__ void __launch_bounds__(512, 1) k_accum_l2(const float* __restrict__ lut,
                                                     const float* __restrict__ scale,
                                                     const float* __restrict__ bias) {
    accum12_body(g_idx2, lut, scale, bias, g_out2);
}

// ---------------- encode3 (unchanged, passing) ----------------
__global__ void __launch_bounds__(64) k_encode3(const float* __restrict__ cent) {
    const int b = blockIdx.y, h = blockIdx.x, cb = threadIdx.x;
    float c[16][4], c2[16];
#pragma unroll
    for (int k = 0; k < 16; k++) {
#pragma unroll
        for (int j = 0; j < 4; j++) c[k][j] = cent[(cb * 16 + k) * 4 + j];
        float s = __fmul_rn(c[k][0], c[k][0]);
        s = __fadd_rn(s, __fmul_rn(c[k][1], c[k][1]));
        s = __fadd_rn(s, __fmul_rn(c[k][2], c[k][2]));
        s = __fadd_rn(s, __fmul_rn(c[k][3], c[k][3]));
        c2[k] = s;
    }
    for (int w = 0; w < NH; w++) {
        const int p = h * NH + w;
        const float4 v = *(const float4*)&g_out2[(b * PP + p) * 256 + cb * 4];
        float best = 3.4e38f; int bi = 0;
#pragma unroll
        for (int k = 0; k < 16; k++) {
            float d = __fmaf_rn(v.x, c[k][0], 0.0f);
            d = __fmaf_rn(v.y, c[k][1], d);
            d = __fmaf_rn(v.z, c[k][2], d);
            d = __fmaf_rn(v.w, c[k][3], d);
            const float s = __fadd_rn(c2[k], -__fmul_rn(2.0f, d));
            if (s < best) { best = s; bi = k; }
        }
        ((unsigned char*)g_idx3)[(b * PP + p) * 64 + cb] = (unsigned char)bi;
    }
}

// ===================================================================
// accum3 (R14, passing): flat grid 296 = 148 tiles x 2 o-halves.
// dyn smem = 2*65536 + 43*64 = 133888.
// ===================================================================
__global__ void __launch_bounds__(512, 1) k_accum3(const float* __restrict__ lut,
                                                   const float* __restrict__ scale,
                                                   const float* __restrict__ bias,
                                                   const float* __restrict__ xin,
                                                   float* __restrict__ out) {
    extern __shared__ float sm[];
    float* lutS = sm;
    unsigned char* idxB = (unsigned char*)(sm + 2 * 16384);
    const int gx = blockIdx.x, t = threadIdx.x;
    const int tile = gx >> 1, oh = gx & 1;
    const int cnt = (tile < 56) ? 43 : 42;
    const int start = (tile < 56) ? tile * 43 : 56 * 43 + (tile - 56) * 42;
    const int og = t & 127, ps = t >> 7;
    const unsigned int* gi = (const unsigned int*)((const unsigned char*)g_idx3 + start * 64);
    for (int i = t; i < cnt * 16; i += 512) ((unsigned int*)idxB)[i] = gi[i];
    float4 acc[11];
#pragma unroll
    for (int i = 0; i < 11; i++) acc[i] = make_float4(0.f, 0.f, 0.f, 0.f);
    const unsigned int sbase = (unsigned int)__cvta_generic_to_shared(lutS);
    const float4* gl = (const float4*)lut;
#pragma unroll
    for (int i = 0; i < 8; i++) {
        const int e4 = i * 512 + t;
        const int row = e4 >> 7, c4 = e4 & 127;
        cp16(sbase + e4 * 16, (const void*)(gl + row * 256 + oh * 128 + c4));
    }
    cpcommit();
    int buf = 0;
    for (int c2 = 0; c2 < 32; c2++) {
        if (c2 + 1 < 32) {
            const unsigned int d0 = sbase + (unsigned int)(buf ^ 1) * 65536u;
#pragma unroll
            for (int i = 0; i < 8; i++) {
                const int e4 = i * 512 + t;
                const int row = e4 >> 7, c4 = e4 & 127;
                cp16(d0 + e4 * 16, (const void*)(gl + ((c2 + 1) * 32 + row) * 256 + oh * 128 + c4));
            }
            cpcommit();
            cpwait1();
        } else {
            cpwait0();
        }
        __syncthreads();
        const float* L = lutS + buf * 16384;
#pragma unroll
        for (int i = 0; i < 11; i++) {
            const int p = ps + 4 * i;
            if (p < cnt) {
                const unsigned char* ib = idxB + p * 64 + (c2 << 1);
#pragma unroll
                for (int j = 0; j < 2; j++) {
                    const unsigned int idx = ib[j];
                    const float4 lv = *(const float4*)(L + (((j << 4) + idx) << 9) + (og << 2));
                    acc[i].x = __fadd_rn(acc[i].x, lv.x);
                    acc[i].y = __fadd_rn(acc[i].y, lv.y);
                    acc[i].z = __fadd_rn(acc[i].z, lv.z);
                    acc[i].w = __fadd_rn(acc[i].w, lv.w);
                }
            }
        }
        __syncthreads();
        buf ^= 1;
    }
    float* tr = lutS;   // 512*45 floats = 92160 B
    __syncthreads();
#pragma unroll
    for (int i = 0; i < 11; i++) {
        const int p = ps + 4 * i;
        if (p < cnt) {
            tr[(og * 4 + 0) * 45 + p] = acc[i].x;
            tr[(og * 4 + 1) * 45 + p] = acc[i].y;
            tr[(og * 4 + 2) * 45 + p] = acc[i].z;
            tr[(og * 4 + 3) * 45 + p] = acc[i].w;
        }
    }
    __syncthreads();
    {
        const int ol = t;
        if (ol < 512) {
            const int O = oh * 512 + ol;
            const float scv = scale[O], biv = bias[O];
            const float* trr = tr + ol * 45;
            for (int p = 0; p < cnt; p++) {
                const int P = start + p;
                const int bb = P / 196, pp = P % 196;
                const int addr = (bb * 1024 + O) * PP + pp;
                float r = __fadd_rn(__fadd_rn(__fmul_rn(trr[p], scv), biv), xin[addr]);
                out[addr] = fmaxf(r, 0.0f);
            }
        }
    }
}

extern "C" void kernel_launch(void* const* d_in, const int* in_sizes, int n_in,
                              void* d_out, int out_size) {
    const float* x   = (const float*)d_in[0];
    const float* c1c = (const float*)d_in[1];
    const float* c1l = (const float*)d_in[2];
    const float* c1s = (const float*)d_in[3];
    const float* c1b = (const float*)d_in[4];
    const float* c2c = (const float*)d_in[5];
    const float* c2l = (const float*)d_in[6];
    const float* c2s = (const float*)d_in[7];
    const float* c2b = (const float*)d_in[8];
    const float* c3c = (const float*)d_in[9];
    const float* c3l = (const float*)d_in[10];
    const float* c3s = (const float*)d_in[11];
    const float* c3b = (const float*)d_in[12];
    float* out = (float*)d_out;

    cudaFuncSetAttribute(k_encode1,  cudaFuncAttributeMaxDynamicSharedMemorySize, 57344);
    cudaFuncSetAttribute(k_encode2,  cudaFuncAttributeMaxDynamicSharedMemorySize, 147456);
    cudaFuncSetAttribute(k_accum_l1, cudaFuncAttributeMaxDynamicSharedMemorySize, 142080);
    cudaFuncSetAttribute(k_accum_l2, cudaFuncAttributeMaxDynamicSharedMemorySize, 142080);
    cudaFuncSetAttribute(k_accum3,   cudaFuncAttributeMaxDynamicSharedMemorySize, 133888);

    k_encode1<<<dim3(NH, BB), 256, 57344>>>(x, c1c);
    k_accum_l1<<<dim3(148), 512, 142080>>>(c1l, c1s, c1b);
    k_encode2<<<dim3(NH, BB), 256, 147456>>>(c2c);
    k_accum_l2<<<dim3(148), 512, 142080>>>(c2l, c2s, c2b);
    k_encode3<<<dim3(NH, BB), 64>>>(c3c);
    k_accum3<<<dim3(296), 512, 133888>>>(c3l, c3s, c3b, x, out);
    (void)in_sizes; (void)n_in; (void)out_size;
}

// round 16
// speedup vs baseline: 1.3928x; 1.1024x over previous
#include <cuda_runtime.h>

#define BB 32
#define PP 196
#define NH 14

static __device__ unsigned int g_idx1[BB * PP * 64];
static __device__ float        g_out1[BB * PP * 256];
static __device__ unsigned int g_idx2[BB * PP * 64];
static __device__ unsigned int g_idx3[BB * PP * 16];

__device__ __forceinline__ void cp16(unsigned int dst, const void* src) {
    asm volatile("cp.async.cg.shared.global [%0], [%1], 16;\n" :: "r"(dst), "l"(src));
}
__device__ __forceinline__ void cpcommit() { asm volatile("cp.async.commit_group;\n" ::: "memory"); }
__device__ __forceinline__ void cpwait0()  { asm volatile("cp.async.wait_group 0;\n" ::: "memory"); }
__device__ __forceinline__ void cpwait1()  { asm volatile("cp.async.wait_group 1;\n" ::: "memory"); }

// ---------------- encode1: smem-staged x tile, FMA dots. dyn smem 57344 ----------------
__global__ void __launch_bounds__(256) k_encode1(const float* __restrict__ x,
                                                 const float* __restrict__ cent) {
    extern __shared__ float xs[];   // [c][w]: 1024*14 floats
    const int b = blockIdx.y, h = blockIdx.x, cb = threadIdx.x;
    for (int i = cb; i < 1024 * 14; i += 256) {
        const int c = i / 14, w = i % 14;
        xs[i] = x[(b * 1024 + c) * PP + h * NH + w];
    }
    float c[16][4], c2[16];
#pragma unroll
    for (int k = 0; k < 16; k++) {
#pragma unroll
        for (int j = 0; j < 4; j++) c[k][j] = cent[(cb * 16 + k) * 4 + j];
        float s = __fmul_rn(c[k][0], c[k][0]);
        s = __fadd_rn(s, __fmul_rn(c[k][1], c[k][1]));
        s = __fadd_rn(s, __fmul_rn(c[k][2], c[k][2]));
        s = __fadd_rn(s, __fmul_rn(c[k][3], c[k][3]));
        c2[k] = s;
    }
    __syncthreads();
    for (int w = 0; w < NH; w++) {
        const float v0 = xs[(cb * 4 + 0) * 14 + w];
        const float v1 = xs[(cb * 4 + 1) * 14 + w];
        const float v2 = xs[(cb * 4 + 2) * 14 + w];
        const float v3 = xs[(cb * 4 + 3) * 14 + w];
        float best = 3.4e38f; int bi = 0;
#pragma unroll
        for (int k = 0; k < 16; k++) {
            float d = __fmaf_rn(v0, c[k][0], 0.0f);
            d = __fmaf_rn(v1, c[k][1], d);
            d = __fmaf_rn(v2, c[k][2], d);
            d = __fmaf_rn(v3, c[k][3], d);
            const float s = __fadd_rn(c2[k], -__fmul_rn(2.0f, d));
            if (s < best) { best = s; bi = k; }
        }
        ((unsigned char*)g_idx1)[(b * PP + h * NH + w) * 256 + cb] = (unsigned char)bi;
    }
}

// ===================================================================
// encode2: 2-pass k-split (k 0-7 then 8-15), carried (best,bi).
// dyn smem = 72*256*4 = 73728 -> 2 blocks/SM, 1.51 waves.
// Arithmetic per k identical to 1-pass version; strict ascending-k argmin.
// ===================================================================
__global__ void __launch_bounds__(256) k_encode2(const float* __restrict__ cent) {
    extern __shared__ float sc[];   // 72 rows x 256
    const int b = blockIdx.y, h = blockIdx.x, c = threadIdx.x;
    float best[14]; int bi[14];
#pragma unroll
    for (int w = 0; w < NH; w++) { best[w] = 3.4e38f; bi[w] = 0; }
    for (int half = 0; half < 2; half++) {
        __syncthreads();   // protect sc reuse across passes
        for (int r = 0; r < 72; r++) sc[r * 256 + c] = cent[c * 144 + half * 72 + r];
        float c2h[8];
#pragma unroll
        for (int kk = 0; kk < 8; kk++) {
            const int base = c * 144 + (half * 8 + kk) * 9;
            float t0 = cent[base];
            float s = __fmul_rn(t0, t0);
#pragma unroll
            for (int t = 1; t < 9; t++) {
                const float tv = cent[base + t];
                s = __fadd_rn(s, __fmul_rn(tv, tv));
            }
            c2h[kk] = s;
        }
        __syncthreads();
        for (int w = 0; w < NH; w++) {
            float v[9];
#pragma unroll
            for (int i = 0; i < 3; i++)
#pragma unroll
                for (int j = 0; j < 3; j++) {
                    const int hh = h - 1 + i, ww = w - 1 + j;
                    float val = 0.0f;
                    if (hh >= 0 && hh < NH && ww >= 0 && ww < NH)
                        val = g_out1[(b * PP + hh * NH + ww) * 256 + c];
                    v[i * 3 + j] = val;
                }
#pragma unroll
            for (int kk = 0; kk < 8; kk++) {
                float d = __fmaf_rn(v[0], sc[(kk * 9 + 0) * 256 + c], 0.0f);
#pragma unroll
                for (int t = 1; t < 9; t++) d = __fmaf_rn(v[t], sc[(kk * 9 + t) * 256 + c], d);
                const float s = __fadd_rn(c2h[kk], -__fmul_rn(2.0f, d));
                if (s < best[w]) { best[w] = s; bi[w] = half * 8 + kk; }
            }
        }
    }
#pragma unroll
    for (int w = 0; w < NH; w++)
        ((unsigned char*)g_idx2)[(b * PP + h * NH + w) * 256 + c] = (unsigned char)bi[w];
}

// ===================================================================
// accum_l1 (R15, passing): kc=248 fold, flat 148 blocks, 512 thr.
// dyn smem = 2*65536 + 43*64*4 = 142080.
// ===================================================================
__global__ void __launch_bounds__(512, 1) k_accum_l1(const float* __restrict__ lut,
                                                     const float* __restrict__ scale,
                                                     const float* __restrict__ bias) {
    extern __shared__ float sm[];
    float* lutS = sm;
    unsigned int* idxS = (unsigned int*)(sm + 2 * 16384);
    const int gx = blockIdx.x, t = threadIdx.x;
    const int og = t & 63, ps = t >> 6;
    const int cnt = (gx < 56) ? 43 : 42;
    const int start = (gx < 56) ? gx * 43 : 56 * 43 + (gx - 56) * 42;
    const unsigned int* gi = g_idx1 + start * 64;
    for (int i = t; i < cnt * 64; i += 512) idxS[i] = gi[i];
    float4 acc[6], tot[6];
#pragma unroll
    for (int i = 0; i < 6; i++) {
        acc[i] = make_float4(0.f, 0.f, 0.f, 0.f);
        tot[i] = make_float4(0.f, 0.f, 0.f, 0.f);
    }
    const unsigned int sbase = (unsigned int)__cvta_generic_to_shared(lutS);
    const float4* gl = (const float4*)lut;
#pragma unroll
    for (int i = 0; i < 8; i++) cp16(sbase + (t + i * 512) * 16, (const void*)(gl + t + i * 512));
    cpcommit();
    int buf = 0;
    for (int ch = 0; ch < 64; ch++) {
        if (ch + 1 < 64) {
            const float4* s = gl + (ch + 1) * 4096;
            const unsigned int d0 = sbase + (unsigned int)(buf ^ 1) * 65536u;
#pragma unroll
            for (int i = 0; i < 8; i++) cp16(d0 + (t + i * 512) * 16, (const void*)(s + t + i * 512));
            cpcommit();
            cpwait1();
        } else {
            cpwait0();
        }
        __syncthreads();
        const float* L = lutS + buf * 16384;
        int fB[4], fC[4], Tt[4], any = 0;
#pragma unroll
        for (int j = 0; j < 4; j++) {
            const int c = (ch << 2) + j, k16 = c << 4;
            fB[j] = ((k16 % 248) == 0 && c > 0) ? 1 : 0;
            const int pan0 = k16 / 248, pan1 = (k16 + 15) / 248;
            fC[j] = (!fB[j] && pan1 > pan0) ? 1 : 0;
            Tt[j] = pan1 * 248 - k16;
            any |= fB[j] | fC[j];
        }
        if (!any) {
#pragma unroll
            for (int i = 0; i < 6; i++) {
                const int p = ps + 8 * i;
                if (p < cnt) {
                    const unsigned int wv = idxS[p * 64 + ch];
#pragma unroll
                    for (int j = 0; j < 4; j++) {
                        const unsigned int idx = (wv >> (8 * j)) & 255u;
                        const float4 lv = *(const float4*)(L + (((j << 4) + idx) << 8) + (og << 2));
                        acc[i].x = __fadd_rn(acc[i].x, lv.x);
                        acc[i].y = __fadd_rn(acc[i].y, lv.y);
                        acc[i].z = __fadd_rn(acc[i].z, lv.z);
                        acc[i].w = __fadd_rn(acc[i].w, lv.w);
                    }
                }
            }
        } else {
#pragma unroll
            for (int i = 0; i < 6; i++) {
                const int p = ps + 8 * i;
                if (p < cnt) {
                    const unsigned int wv = idxS[p * 64 + ch];
#pragma unroll
                    for (int j = 0; j < 4; j++) {
                        const unsigned int idx = (wv >> (8 * j)) & 255u;
                        const float4 lv = *(const float4*)(L + (((j << 4) + idx) << 8) + (og << 2));
                        const bool foldB = fB[j] || (fC[j] && (int)idx >= Tt[j]);
                        if (foldB) {
                            tot[i].x = __fadd_rn(tot[i].x, acc[i].x); acc[i].x = lv.x;
                            tot[i].y = __fadd_rn(tot[i].y, acc[i].y); acc[i].y = lv.y;
                            tot[i].z = __fadd_rn(tot[i].z, acc[i].z); acc[i].z = lv.z;
                            tot[i].w = __fadd_rn(tot[i].w, acc[i].w); acc[i].w = lv.w;
                        } else {
                            acc[i].x = __fadd_rn(acc[i].x, lv.x);
                            acc[i].y = __fadd_rn(acc[i].y, lv.y);
                            acc[i].z = __fadd_rn(acc[i].z, lv.z);
                            acc[i].w = __fadd_rn(acc[i].w, lv.w);
                            if (fC[j]) {
                                tot[i].x = __fadd_rn(tot[i].x, acc[i].x); acc[i].x = 0.f;
                                tot[i].y = __fadd_rn(tot[i].y, acc[i].y); acc[i].y = 0.f;
                                tot[i].z = __fadd_rn(tot[i].z, acc[i].z); acc[i].z = 0.f;
                                tot[i].w = __fadd_rn(tot[i].w, acc[i].w); acc[i].w = 0.f;
                            }
                        }
                    }
                }
            }
        }
        __syncthreads();
        buf ^= 1;
    }
    const float4 sc4 = ((const float4*)scale)[og];
    const float4 bi4 = ((const float4*)bias)[og];
#pragma unroll
    for (int i = 0; i < 6; i++) {
        const int p = ps + 8 * i;
        if (p < cnt) {
            float4 r; float s;
            s = __fadd_rn(tot[i].x, acc[i].x); r.x = fmaxf(__fadd_rn(__fmul_rn(s, sc4.x), bi4.x), 0.0f);
            s = __fadd_rn(tot[i].y, acc[i].y); r.y = fmaxf(__fadd_rn(__fmul_rn(s, sc4.y), bi4.y), 0.0f);
            s = __fadd_rn(tot[i].z, acc[i].z); r.z = fmaxf(__fadd_rn(__fmul_rn(s, sc4.z), bi4.z), 0.0f);
            s = __fadd_rn(tot[i].w, acc[i].w); r.w = fmaxf(__fadd_rn(__fmul_rn(s, sc4.w), bi4.w), 0.0f);
            *(float4*)(g_out1 + (start + p) * 256 + (og << 2)) = r;
        }
    }
}

// ===================================================================
// accum_l2 FUSED with encode3: same mainloop as accum_l1, but the
// BN+relu results go to SMEM (reusing lutS) and the layer-3 PQ encode
// (64 codebooks, dsub=4) runs inline -> writes g_idx3. No g_out2.
// dyn smem = 2*65536 + 43*64*4 + 4096*4 = 158464.
// ===================================================================
__global__ void __launch_bounds__(512, 1) k_accum_l2f(const float* __restrict__ lut,
                                                      const float* __restrict__ scale,
                                                      const float* __restrict__ bias,
                                                      const float* __restrict__ cent3) {
    extern __shared__ float sm[];
    float* lutS = sm;                                         // 2*16384 floats
    unsigned int* idxS = (unsigned int*)(sm + 2 * 16384);     // 2752 words
    float* sc3 = sm + 2 * 16384 + 2752;                       // 4096 floats, [k*4+j][cb]
    const int gx = blockIdx.x, t = threadIdx.x;
    const int og = t & 63, ps = t >> 6;
    const int cnt = (gx < 56) ? 43 : 42;
    const int start = (gx < 56) ? gx * 43 : 56 * 43 + (gx - 56) * 42;
    const unsigned int* gi = g_idx2 + start * 64;
    for (int i = t; i < cnt * 64; i += 512) idxS[i] = gi[i];
    // stage c3 centroids transposed: sc3[(k*4+j)*64 + cb] = cent3[cb*64 + k*4 + j]
    for (int i = t; i < 4096; i += 512) sc3[(i & 63) * 64 + (i >> 6)] = cent3[i];
    float4 acc[6], tot[6];
#pragma unroll
    for (int i = 0; i < 6; i++) {
        acc[i] = make_float4(0.f, 0.f, 0.f, 0.f);
        tot[i] = make_float4(0.f, 0.f, 0.f, 0.f);
    }
    const unsigned int sbase = (unsigned int)__cvta_generic_to_shared(lutS);
    const float4* gl = (const float4*)lut;
#pragma unroll
    for (int i = 0; i < 8; i++) cp16(sbase + (t + i * 512) * 16, (const void*)(gl + t + i * 512));
    cpcommit();
    int buf = 0;
    for (int ch = 0; ch < 64; ch++) {
        if (ch + 1 < 64) {
            const float4* s = gl + (ch + 1) * 4096;
            const unsigned int d0 = sbase + (unsigned int)(buf ^ 1) * 65536u;
#pragma unroll
            for (int i = 0; i < 8; i++) cp16(d0 + (t + i * 512) * 16, (const void*)(s + t + i * 512));
            cpcommit();
            cpwait1();
        } else {
            cpwait0();
        }
        __syncthreads();
        const float* L = lutS + buf * 16384;
        int fB[4], fC[4], Tt[4], any = 0;
#pragma unroll
        for (int j = 0; j < 4; j++) {
            const int c = (ch << 2) + j, k16 = c << 4;
            fB[j] = ((k16 % 248) == 0 && c > 0) ? 1 : 0;
            const int pan0 = k16 / 248, pan1 = (k16 + 15) / 248;
            fC[j] = (!fB[j] && pan1 > pan0) ? 1 : 0;
            Tt[j] = pan1 * 248 - k16;
            any |= fB[j] | fC[j];
        }
        if (!any) {
#pragma unroll
            for (int i = 0; i < 6; i++) {
                const int p = ps + 8 * i;
                if (p < cnt) {
                    const unsigned int wv = idxS[p * 64 + ch];
#pragma unroll
                    for (int j = 0; j < 4; j++) {
                        const unsigned int idx = (wv >> (8 * j)) & 255u;
                        const float4 lv = *(const float4*)(L + (((j << 4) + idx) << 8) + (og << 2));
                        acc[i].x = __fadd_rn(acc[i].x, lv.x);
                        acc[i].y = __fadd_rn(acc[i].y, lv.y);
                        acc[i].z = __fadd_rn(acc[i].z, lv.z);
                        acc[i].w = __fadd_rn(acc[i].w, lv.w);
                    }
                }
            }
        } else {
#pragma unroll
            for (int i = 0; i < 6; i++) {
                const int p = ps + 8 * i;
                if (p < cnt) {
                    const unsigned int wv = idxS[p * 64 + ch];
#pragma unroll
                    for (int j = 0; j < 4; j++) {
                        const unsigned int idx = (wv >> (8 * j)) & 255u;
                        const float4 lv = *(const float4*)(L + (((j << 4) + idx) << 8) + (og << 2));
                        const bool foldB = fB[j] || (fC[j] && (int)idx >= Tt[j]);
                        if (foldB) {
                            tot[i].x = __fadd_rn(tot[i].x, acc[i].x); acc[i].x = lv.x;
                            tot[i].y = __fadd_rn(tot[i].y, acc[i].y); acc[i].y = lv.y;
                            tot[i].z = __fadd_rn(tot[i].z, acc[i].z); acc[i].z = lv.z;
                            tot[i].w = __fadd_rn(tot[i].w, acc[i].w); acc[i].w = lv.w;
                        } else {
                            acc[i].x = __fadd_rn(acc[i].x, lv.x);
                            acc[i].y = __fadd_rn(acc[i].y, lv.y);
                            acc[i].z = __fadd_rn(acc[i].z, lv.z);
                            acc[i].w = __fadd_rn(acc[i].w, lv.w);
                            if (fC[j]) {
                                tot[i].x = __fadd_rn(tot[i].x, acc[i].x); acc[i].x = 0.f;
                                tot[i].y = __fadd_rn(tot[i].y, acc[i].y); acc[i].y = 0.f;
                                tot[i].z = __fadd_rn(tot[i].z, acc[i].z); acc[i].z = 0.f;
                                tot[i].w = __fadd_rn(tot[i].w, acc[i].w); acc[i].w = 0.f;
                            }
                        }
                    }
                }
            }
        }
        __syncthreads();
        buf ^= 1;
    }
    // BN + relu into SMEM (reuse lutS), then inline encode3
    const float4 sc4 = ((const float4*)scale)[og];
    const float4 bi4 = ((const float4*)bias)[og];
    float* outS = lutS;   // 43*256 floats = 44032 B, fits in lutS region
    __syncthreads();      // all done reading lutS
#pragma unroll
    for (int i = 0; i < 6; i++) {
        const int p = ps + 8 * i;
        if (p < cnt) {
            float4 r; float s;
            s = __fadd_rn(tot[i].x, acc[i].x); r.x = fmaxf(__fadd_rn(__fmul_rn(s, sc4.x), bi4.x), 0.0f);
            s = __fadd_rn(tot[i].y, acc[i].y); r.y = fmaxf(__fadd_rn(__fmul_rn(s, sc4.y), bi4.y), 0.0f);
            s = __fadd_rn(tot[i].z, acc[i].z); r.z = fmaxf(__fadd_rn(__fmul_rn(s, sc4.z), bi4.z), 0.0f);
            s = __fadd_rn(tot[i].w, acc[i].w); r.w = fmaxf(__fadd_rn(__fmul_rn(s, sc4.w), bi4.w), 0.0f);
            *(float4*)(outS + p * 256 + (og << 2)) = r;
        }
    }
    __syncthreads();
    // encode3 inline: tasks (p, cb), strict ascending-k first-min argmin
    for (int task = t; task < cnt * 64; task += 512) {
        const int p = task >> 6, cb = task & 63;
        const float4 v = *(const float4*)(outS + p * 256 + (cb << 2));
        float best = 3.4e38f; int bik = 0;
#pragma unroll
        for (int k = 0; k < 16; k++) {
            const float c0 = sc3[(k * 4 + 0) * 64 + cb];
            const float c1 = sc3[(k * 4 + 1) * 64 + cb];
            const float c2v = sc3[(k * 4 + 2) * 64 + cb];
            const float c3v = sc3[(k * 4 + 3) * 64 + cb];
            float s2 = __fmul_rn(c0, c0);
            s2 = __fadd_rn(s2, __fmul_rn(c1, c1));
            s2 = __fadd_rn(s2, __fmul_rn(c2v, c2v));
            s2 = __fadd_rn(s2, __fmul_rn(c3v, c3v));
            float d = __fmaf_rn(v.x, c0, 0.0f);
            d = __fmaf_rn(v.y, c1, d);
            d = __fmaf_rn(v.z, c2v, d);
            d = __fmaf_rn(v.w, c3v, d);
            const float s = __fadd_rn(s2, -__fmul_rn(2.0f, d));
            if (s < best) { best = s; bik = k; }
        }
        ((unsigned char*)g_idx3)[(start + p) * 64 + cb] = (unsigned char)bik;
    }
}

// ===================================================================
// accum3 (R14/R15, passing): flat grid 296 = 148 tiles x 2 o-halves.
// dyn smem = 2*65536 + 43*64 = 133888.
// ===================================================================
__global__ void __launch_bounds__(512, 1) k_accum3(const float* __restrict__ lut,
                                                   const float* __restrict__ scale,
                                                   const float* __restrict__ bias,
                                                   const float* __restrict__ xin,
                                                   float* __restrict__ out) {
    extern __shared__ float sm[];
    float* lutS = sm;
    unsigned char* idxB = (unsigned char*)(sm + 2 * 16384);
    const int gx = blockIdx.x, t = threadIdx.x;
    const int tile = gx >> 1, oh = gx & 1;
    const int cnt = (tile < 56) ? 43 : 42;
    const int start = (tile < 56) ? tile * 43 : 56 * 43 + (tile - 56) * 42;
    const int og = t & 127, ps = t >> 7;
    const unsigned int* gi = (const unsigned int*)((const unsigned char*)g_idx3 + start * 64);
    for (int i = t; i < cnt * 16; i += 512) ((unsigned int*)idxB)[i] = gi[i];
    float4 acc[11];
#pragma unroll
    for (int i = 0; i < 11; i++) acc[i] = make_float4(0.f, 0.f, 0.f, 0.f);
    const unsigned int sbase = (unsigned int)__cvta_generic_to_shared(lutS);
    const float4* gl = (const float4*)lut;
#pragma unroll
    for (int i = 0; i < 8; i++) {
        const int e4 = i * 512 + t;
        const int row = e4 >> 7, c4 = e4 & 127;
        cp16(sbase + e4 * 16, (const void*)(gl + row * 256 + oh * 128 + c4));
    }
    cpcommit();
    int buf = 0;
    for (int c2 = 0; c2 < 32; c2++) {
        if (c2 + 1 < 32) {
            const unsigned int d0 = sbase + (unsigned int)(buf ^ 1) * 65536u;
#pragma unroll
            for (int i = 0; i < 8; i++) {
                const int e4 = i * 512 + t;
                const int row = e4 >> 7, c4 = e4 & 127;
                cp16(d0 + e4 * 16, (const void*)(gl + ((c2 + 1) * 32 + row) * 256 + oh * 128 + c4));
            }
            cpcommit();
            cpwait1();
        } else {
            cpwait0();
        }
        __syncthreads();
        const float* L = lutS + buf * 16384;
#pragma unroll
        for (int i = 0; i < 11; i++) {
            const int p = ps + 4 * i;
            if (p < cnt) {
                const unsigned char* ib = idxB + p * 64 + (c2 << 1);
#pragma unroll
                for (int j = 0; j < 2; j++) {
                    const unsigned int idx = ib[j];
                    const float4 lv = *(const float4*)(L + (((j << 4) + idx) << 9) + (og << 2));
                    acc[i].x = __fadd_rn(acc[i].x, lv.x);
                    acc[i].y = __fadd_rn(acc[i].y, lv.y);
                    acc[i].z = __fadd_rn(acc[i].z, lv.z);
                    acc[i].w = __fadd_rn(acc[i].w, lv.w);
                }
            }
        }
        __syncthreads();
        buf ^= 1;
    }
    float* tr = lutS;   // 512*45 floats = 92160 B
    __syncthreads();
#pragma unroll
    for (int i = 0; i < 11; i++) {
        const int p = ps + 4 * i;
        if (p < cnt) {
            tr[(og * 4 + 0) * 45 + p] = acc[i].x;
            tr[(og * 4 + 1) * 45 + p] = acc[i].y;
            tr[(og * 4 + 2) * 45 + p] = acc[i].z;
            tr[(og * 4 + 3) * 45 + p] = acc[i].w;
        }
    }
    __syncthreads();
    {
        const int ol = t;
        if (ol < 512) {
            const int O = oh * 512 + ol;
            const float scv = scale[O], biv = bias[O];
            const float* trr = tr + ol * 45;
            for (int p = 0; p < cnt; p++) {
                const int P = start + p;
                const int bb = P / 196, pp = P % 196;
                const int addr = (bb * 1024 + O) * PP + pp;
                float r = __fadd_rn(__fadd_rn(__fmul_rn(trr[p], scv), biv), xin[addr]);
                out[addr] = fmaxf(r, 0.0f);
            }
        }
    }
}

extern "C" void kernel_launch(void* const* d_in, const int* in_sizes, int n_in,
                              void* d_out, int out_size) {
    const float* x   = (const float*)d_in[0];
    const float* c1c = (const float*)d_in[1];
    const float* c1l = (const float*)d_in[2];
    const float* c1s = (const float*)d_in[3];
    const float* c1b = (const float*)d_in[4];
    const float* c2c = (const float*)d_in[5];
    const float* c2l = (const float*)d_in[6];
    const float* c2s = (const float*)d_in[7];
    const float* c2b = (const float*)d_in[8];
    const float* c3c = (const float*)d_in[9];
    const float* c3l = (const float*)d_in[10];
    const float* c3s = (const float*)d_in[11];
    const float* c3b = (const float*)d_in[12];
    float* out = (float*)d_out;

    cudaFuncSetAttribute(k_encode1,  cudaFuncAttributeMaxDynamicSharedMemorySize, 57344);
    cudaFuncSetAttribute(k_encode2,  cudaFuncAttributeMaxDynamicSharedMemorySize, 73728);
    cudaFuncSetAttribute(k_accum_l1, cudaFuncAttributeMaxDynamicSharedMemorySize, 142080);
    cudaFuncSetAttribute(k_accum_l2f, cudaFuncAttributeMaxDynamicSharedMemorySize, 158464);
    cudaFuncSetAttribute(k_accum3,   cudaFuncAttributeMaxDynamicSharedMemorySize, 133888);

    k_encode1<<<dim3(NH, BB), 256, 57344>>>(x, c1c);
    k_accum_l1<<<dim3(148), 512, 142080>>>(c1l, c1s, c1b);
    k_encode2<<<dim3(NH, BB), 256, 73728>>>(c2c);
    k_accum_l2f<<<dim3(148), 512, 158464>>>(c2l, c2s, c2b, c3c);
    k_accum3<<<dim3(296), 512, 133888>>>(c3l, c3s, c3b, x, out);
    (void)in_sizes; (void)n_in; (void)out_size;
}

// round 17
// speedup vs baseline: 1.4258x; 1.0236x over previous
#include <cuda_runtime.h>

#define BB 32
#define PP 196
#define NH 14

static __device__ unsigned int g_idx1[BB * PP * 64];
static __device__ float        g_out1[BB * PP * 256];
static __device__ unsigned int g_idx2[BB * PP * 64];
static __device__ unsigned int g_idx3[BB * PP * 16];

__device__ __forceinline__ void cp16(unsigned int dst, const void* src) {
    asm volatile("cp.async.cg.shared.global [%0], [%1], 16;\n" :: "r"(dst), "l"(src));
}
__device__ __forceinline__ void cpcommit() { asm volatile("cp.async.commit_group;\n" ::: "memory"); }
__device__ __forceinline__ void cpwait0()  { asm volatile("cp.async.wait_group 0;\n" ::: "memory"); }
__device__ __forceinline__ void cpwait1()  { asm volatile("cp.async.wait_group 1;\n" ::: "memory"); }

// ---------------- encode1 (unchanged, passing). dyn smem 57344 ----------------
__global__ void __launch_bounds__(256) k_encode1(const float* __restrict__ x,
                                                 const float* __restrict__ cent) {
    extern __shared__ float xs[];   // [c][w]: 1024*14 floats
    const int b = blockIdx.y, h = blockIdx.x, cb = threadIdx.x;
    for (int i = cb; i < 1024 * 14; i += 256) {
        const int c = i / 14, w = i % 14;
        xs[i] = x[(b * 1024 + c) * PP + h * NH + w];
    }
    float c[16][4], c2[16];
#pragma unroll
    for (int k = 0; k < 16; k++) {
#pragma unroll
        for (int j = 0; j < 4; j++) c[k][j] = cent[(cb * 16 + k) * 4 + j];
        float s = __fmul_rn(c[k][0], c[k][0]);
        s = __fadd_rn(s, __fmul_rn(c[k][1], c[k][1]));
        s = __fadd_rn(s, __fmul_rn(c[k][2], c[k][2]));
        s = __fadd_rn(s, __fmul_rn(c[k][3], c[k][3]));
        c2[k] = s;
    }
    __syncthreads();
    for (int w = 0; w < NH; w++) {
        const float v0 = xs[(cb * 4 + 0) * 14 + w];
        const float v1 = xs[(cb * 4 + 1) * 14 + w];
        const float v2 = xs[(cb * 4 + 2) * 14 + w];
        const float v3 = xs[(cb * 4 + 3) * 14 + w];
        float best = 3.4e38f; int bi = 0;
#pragma unroll
        for (int k = 0; k < 16; k++) {
            float d = __fmaf_rn(v0, c[k][0], 0.0f);
            d = __fmaf_rn(v1, c[k][1], d);
            d = __fmaf_rn(v2, c[k][2], d);
            d = __fmaf_rn(v3, c[k][3], d);
            const float s = __fadd_rn(c2[k], -__fmul_rn(2.0f, d));
            if (s < best) { best = s; bi = k; }
        }
        ((unsigned char*)g_idx1)[(b * PP + h * NH + w) * 256 + cb] = (unsigned char)bi;
    }
}

// ---------------- encode2 (unchanged, passing). dyn smem 73728 ----------------
__global__ void __launch_bounds__(256) k_encode2(const float* __restrict__ cent) {
    extern __shared__ float sc[];   // 72 rows x 256
    const int b = blockIdx.y, h = blockIdx.x, c = threadIdx.x;
    float best[14]; int bi[14];
#pragma unroll
    for (int w = 0; w < NH; w++) { best[w] = 3.4e38f; bi[w] = 0; }
    for (int half = 0; half < 2; half++) {
        __syncthreads();
        for (int r = 0; r < 72; r++) sc[r * 256 + c] = cent[c * 144 + half * 72 + r];
        float c2h[8];
#pragma unroll
        for (int kk = 0; kk < 8; kk++) {
            const int base = c * 144 + (half * 8 + kk) * 9;
            float t0 = cent[base];
            float s = __fmul_rn(t0, t0);
#pragma unroll
            for (int t = 1; t < 9; t++) {
                const float tv = cent[base + t];
                s = __fadd_rn(s, __fmul_rn(tv, tv));
            }
            c2h[kk] = s;
        }
        __syncthreads();
        for (int w = 0; w < NH; w++) {
            float v[9];
#pragma unroll
            for (int i = 0; i < 3; i++)
#pragma unroll
                for (int j = 0; j < 3; j++) {
                    const int hh = h - 1 + i, ww = w - 1 + j;
                    float val = 0.0f;
                    if (hh >= 0 && hh < NH && ww >= 0 && ww < NH)
                        val = g_out1[(b * PP + hh * NH + ww) * 256 + c];
                    v[i * 3 + j] = val;
                }
#pragma unroll
            for (int kk = 0; kk < 8; kk++) {
                float d = __fmaf_rn(v[0], sc[(kk * 9 + 0) * 256 + c], 0.0f);
#pragma unroll
                for (int t = 1; t < 9; t++) d = __fmaf_rn(v[t], sc[(kk * 9 + t) * 256 + c], d);
                const float s = __fadd_rn(c2h[kk], -__fmul_rn(2.0f, d));
                if (s < best[w]) { best[w] = s; bi[w] = half * 8 + kk; }
            }
        }
    }
#pragma unroll
    for (int w = 0; w < NH; w++)
        ((unsigned char*)g_idx2)[(b * PP + h * NH + w) * 256 + c] = (unsigned char)bi[w];
}

// ===================================================================
// accum_l1: kc=248 fold, O-SPLIT PAIRING: 296 blocks = 148 tiles x 2
// o-halves (128 outputs each) -> 2 blocks/SM, restream unchanged.
// 512 threads = 32 og x 16 ps; p = ps + 16*i (i<3).
// Chunk = 4 cb x 128 o = 32 KB. dyn smem = 2*32768 + 43*64*4 = 76544.
// ===================================================================
__global__ void __launch_bounds__(512, 2) k_accum_l1(const float* __restrict__ lut,
                                                     const float* __restrict__ scale,
                                                     const float* __restrict__ bias) {
    extern __shared__ float sm[];
    float* lutS = sm;                                      // 2 * 8192 floats
    unsigned int* idxS = (unsigned int*)(sm + 2 * 8192);   // cnt*64 words
    const int gx = blockIdx.x, t = threadIdx.x;
    const int tile = gx >> 1, oh = gx & 1;
    const int og = t & 31, ps = t >> 5;                    // ps 0..15
    const int cnt = (tile < 56) ? 43 : 42;
    const int start = (tile < 56) ? tile * 43 : 56 * 43 + (tile - 56) * 42;
    const unsigned int* gi = g_idx1 + start * 64;
    for (int i = t; i < cnt * 64; i += 512) idxS[i] = gi[i];
    float4 acc[3], tot[3];
#pragma unroll
    for (int i = 0; i < 3; i++) {
        acc[i] = make_float4(0.f, 0.f, 0.f, 0.f);
        tot[i] = make_float4(0.f, 0.f, 0.f, 0.f);
    }
    const unsigned int sbase = (unsigned int)__cvta_generic_to_shared(lutS);
    const float4* gl = (const float4*)lut;                 // row = 64 float4
    const int ob = oh * 32;                                // float4 offset of half
#pragma unroll
    for (int i = 0; i < 4; i++) {
        const int e4 = i * 512 + t;                        // 0..2047
        const int row = e4 >> 5, c4 = e4 & 31;
        cp16(sbase + e4 * 16, (const void*)(gl + row * 64 + ob + c4));
    }
    cpcommit();
    int buf = 0;
    for (int ch = 0; ch < 64; ch++) {
        if (ch + 1 < 64) {
            const unsigned int d0 = sbase + (unsigned int)(buf ^ 1) * 32768u;
#pragma unroll
            for (int i = 0; i < 4; i++) {
                const int e4 = i * 512 + t;
                const int row = e4 >> 5, c4 = e4 & 31;
                cp16(d0 + e4 * 16, (const void*)(gl + ((ch + 1) * 64 + row) * 64 + ob + c4));
            }
            cpcommit();
            cpwait1();
        } else {
            cpwait0();
        }
        __syncthreads();
        const float* L = lutS + buf * 8192;                // 64 rows x 128 floats
        int fB[4], fC[4], Tt[4], any = 0;
#pragma unroll
        for (int j = 0; j < 4; j++) {
            const int c = (ch << 2) + j, k16 = c << 4;
            fB[j] = ((k16 % 248) == 0 && c > 0) ? 1 : 0;
            const int pan0 = k16 / 248, pan1 = (k16 + 15) / 248;
            fC[j] = (!fB[j] && pan1 > pan0) ? 1 : 0;
            Tt[j] = pan1 * 248 - k16;
            any |= fB[j] | fC[j];
        }
        if (!any) {
#pragma unroll
            for (int i = 0; i < 3; i++) {
                const int p = ps + 16 * i;
                if (p < cnt) {
                    const unsigned int wv = idxS[p * 64 + ch];
#pragma unroll
                    for (int j = 0; j < 4; j++) {
                        const unsigned int idx = (wv >> (8 * j)) & 255u;
                        const float4 lv = *(const float4*)(L + (((j << 4) + idx) << 7) + (og << 2));
                        acc[i].x = __fadd_rn(acc[i].x, lv.x);
                        acc[i].y = __fadd_rn(acc[i].y, lv.y);
                        acc[i].z = __fadd_rn(acc[i].z, lv.z);
                        acc[i].w = __fadd_rn(acc[i].w, lv.w);
                    }
                }
            }
        } else {
#pragma unroll
            for (int i = 0; i < 3; i++) {
                const int p = ps + 16 * i;
                if (p < cnt) {
                    const unsigned int wv = idxS[p * 64 + ch];
#pragma unroll
                    for (int j = 0; j < 4; j++) {
                        const unsigned int idx = (wv >> (8 * j)) & 255u;
                        const float4 lv = *(const float4*)(L + (((j << 4) + idx) << 7) + (og << 2));
                        const bool foldB = fB[j] || (fC[j] && (int)idx >= Tt[j]);
                        if (foldB) {
                            tot[i].x = __fadd_rn(tot[i].x, acc[i].x); acc[i].x = lv.x;
                            tot[i].y = __fadd_rn(tot[i].y, acc[i].y); acc[i].y = lv.y;
                            tot[i].z = __fadd_rn(tot[i].z, acc[i].z); acc[i].z = lv.z;
                            tot[i].w = __fadd_rn(tot[i].w, acc[i].w); acc[i].w = lv.w;
                        } else {
                            acc[i].x = __fadd_rn(acc[i].x, lv.x);
                            acc[i].y = __fadd_rn(acc[i].y, lv.y);
                            acc[i].z = __fadd_rn(acc[i].z, lv.z);
                            acc[i].w = __fadd_rn(acc[i].w, lv.w);
                            if (fC[j]) {
                                tot[i].x = __fadd_rn(tot[i].x, acc[i].x); acc[i].x = 0.f;
                                tot[i].y = __fadd_rn(tot[i].y, acc[i].y); acc[i].y = 0.f;
                                tot[i].z = __fadd_rn(tot[i].z, acc[i].z); acc[i].z = 0.f;
                                tot[i].w = __fadd_rn(tot[i].w, acc[i].w); acc[i].w = 0.f;
                            }
                        }
                    }
                }
            }
        }
        __syncthreads();
        buf ^= 1;
    }
    const float4 sc4 = ((const float4*)scale)[(oh << 5) + og];
    const float4 bi4 = ((const float4*)bias)[(oh << 5) + og];
#pragma unroll
    for (int i = 0; i < 3; i++) {
        const int p = ps + 16 * i;
        if (p < cnt) {
            float4 r; float s;
            s = __fadd_rn(tot[i].x, acc[i].x); r.x = fmaxf(__fadd_rn(__fmul_rn(s, sc4.x), bi4.x), 0.0f);
            s = __fadd_rn(tot[i].y, acc[i].y); r.y = fmaxf(__fadd_rn(__fmul_rn(s, sc4.y), bi4.y), 0.0f);
            s = __fadd_rn(tot[i].z, acc[i].z); r.z = fmaxf(__fadd_rn(__fmul_rn(s, sc4.z), bi4.z), 0.0f);
            s = __fadd_rn(tot[i].w, acc[i].w); r.w = fmaxf(__fadd_rn(__fmul_rn(s, sc4.w), bi4.w), 0.0f);
            ((float4*)(g_out1 + (start + p) * 256))[(oh << 5) + og] = r;
        }
    }
}

// ===================================================================
// accum_l2 FUSED with encode3 (R16, passing): flat 148 blocks, 512 thr.
// dyn smem = 2*65536 + 43*64*4 + 4096*4 = 158464.
// ===================================================================
__global__ void __launch_bounds__(512, 1) k_accum_l2f(const float* __restrict__ lut,
                                                      const float* __restrict__ scale,
                                                      const float* __restrict__ bias,
                                                      const float* __restrict__ cent3) {
    extern __shared__ float sm[];
    float* lutS = sm;
    unsigned int* idxS = (unsigned int*)(sm + 2 * 16384);
    float* sc3 = sm + 2 * 16384 + 2752;
    const int gx = blockIdx.x, t = threadIdx.x;
    const int og = t & 63, ps = t >> 6;
    const int cnt = (gx < 56) ? 43 : 42;
    const int start = (gx < 56) ? gx * 43 : 56 * 43 + (gx - 56) * 42;
    const unsigned int* gi = g_idx2 + start * 64;
    for (int i = t; i < cnt * 64; i += 512) idxS[i] = gi[i];
    for (int i = t; i < 4096; i += 512) sc3[(i & 63) * 64 + (i >> 6)] = cent3[i];
    float4 acc[6], tot[6];
#pragma unroll
    for (int i = 0; i < 6; i++) {
        acc[i] = make_float4(0.f, 0.f, 0.f, 0.f);
        tot[i] = make_float4(0.f, 0.f, 0.f, 0.f);
    }
    const unsigned int sbase = (unsigned int)__cvta_generic_to_shared(lutS);
    const float4* gl = (const float4*)lut;
#pragma unroll
    for (int i = 0; i < 8; i++) cp16(sbase + (t + i * 512) * 16, (const void*)(gl + t + i * 512));
    cpcommit();
    int buf = 0;
    for (int ch = 0; ch < 64; ch++) {
        if (ch + 1 < 64) {
            const float4* s = gl + (ch + 1) * 4096;
            const unsigned int d0 = sbase + (unsigned int)(buf ^ 1) * 65536u;
#pragma unroll
            for (int i = 0; i < 8; i++) cp16(d0 + (t + i * 512) * 16, (const void*)(s + t + i * 512));
            cpcommit();
            cpwait1();
        } else {
            cpwait0();
        }
        __syncthreads();
        const float* L = lutS + buf * 16384;
        int fB[4], fC[4], Tt[4], any = 0;
#pragma unroll
        for (int j = 0; j < 4; j++) {
            const int c = (ch << 2) + j, k16 = c << 4;
            fB[j] = ((k16 % 248) == 0 && c > 0) ? 1 : 0;
            const int pan0 = k16 / 248, pan1 = (k16 + 15) / 248;
            fC[j] = (!fB[j] && pan1 > pan0) ? 1 : 0;
            Tt[j] = pan1 * 248 - k16;
            any |= fB[j] | fC[j];
        }
        if (!any) {
#pragma unroll
            for (int i = 0; i < 6; i++) {
                const int p = ps + 8 * i;
                if (p < cnt) {
                    const unsigned int wv = idxS[p * 64 + ch];
#pragma unroll
                    for (int j = 0; j < 4; j++) {
                        const unsigned int idx = (wv >> (8 * j)) & 255u;
                        const float4 lv = *(const float4*)(L + (((j << 4) + idx) << 8) + (og << 2));
                        acc[i].x = __fadd_rn(acc[i].x, lv.x);
                        acc[i].y = __fadd_rn(acc[i].y, lv.y);
                        acc[i].z = __fadd_rn(acc[i].z, lv.z);
                        acc[i].w = __fadd_rn(acc[i].w, lv.w);
                    }
                }
            }
        } else {
#pragma unroll
            for (int i = 0; i < 6; i++) {
                const int p = ps + 8 * i;
                if (p < cnt) {
                    const unsigned int wv = idxS[p * 64 + ch];
#pragma unroll
                    for (int j = 0; j < 4; j++) {
                        const unsigned int idx = (wv >> (8 * j)) & 255u;
                        const float4 lv = *(const float4*)(L + (((j << 4) + idx) << 8) + (og << 2));
                        const bool foldB = fB[j] || (fC[j] && (int)idx >= Tt[j]);
                        if (foldB) {
                            tot[i].x = __fadd_rn(tot[i].x, acc[i].x); acc[i].x = lv.x;
                            tot[i].y = __fadd_rn(tot[i].y, acc[i].y); acc[i].y = lv.y;
                            tot[i].z = __fadd_rn(tot[i].z, acc[i].z); acc[i].z = lv.z;
                            tot[i].w = __fadd_rn(tot[i].w, acc[i].w); acc[i].w = lv.w;
                        } else {
                            acc[i].x = __fadd_rn(acc[i].x, lv.x);
                            acc[i].y = __fadd_rn(acc[i].y, lv.y);
                            acc[i].z = __fadd_rn(acc[i].z, lv.z);
                            acc[i].w = __fadd_rn(acc[i].w, lv.w);
                            if (fC[j]) {
                                tot[i].x = __fadd_rn(tot[i].x, acc[i].x); acc[i].x = 0.f;
                                tot[i].y = __fadd_rn(tot[i].y, acc[i].y); acc[i].y = 0.f;
                                tot[i].z = __fadd_rn(tot[i].z, acc[i].z); acc[i].z = 0.f;
                                tot[i].w = __fadd_rn(tot[i].w, acc[i].w); acc[i].w = 0.f;
                            }
                        }
                    }
                }
            }
        }
        __syncthreads();
        buf ^= 1;
    }
    const float4 sc4 = ((const float4*)scale)[og];
    const float4 bi4 = ((const float4*)bias)[og];
    float* outS = lutS;
    __syncthreads();
#pragma unroll
    for (int i = 0; i < 6; i++) {
        const int p = ps + 8 * i;
        if (p < cnt) {
            float4 r; float s;
            s = __fadd_rn(tot[i].x, acc[i].x); r.x = fmaxf(__fadd_rn(__fmul_rn(s, sc4.x), bi4.x), 0.0f);
            s = __fadd_rn(tot[i].y, acc[i].y); r.y = fmaxf(__fadd_rn(__fmul_rn(s, sc4.y), bi4.y), 0.0f);
            s = __fadd_rn(tot[i].z, acc[i].z); r.z = fmaxf(__fadd_rn(__fmul_rn(s, sc4.z), bi4.z), 0.0f);
            s = __fadd_rn(tot[i].w, acc[i].w); r.w = fmaxf(__fadd_rn(__fmul_rn(s, sc4.w), bi4.w), 0.0f);
            *(float4*)(outS + p * 256 + (og << 2)) = r;
        }
    }
    __syncthreads();
    for (int task = t; task < cnt * 64; task += 512) {
        const int p = task >> 6, cb = task & 63;
        const float4 v = *(const float4*)(outS + p * 256 + (cb << 2));
        float best = 3.4e38f; int bik = 0;
#pragma unroll
        for (int k = 0; k < 16; k++) {
            const float c0 = sc3[(k * 4 + 0) * 64 + cb];
            const float c1 = sc3[(k * 4 + 1) * 64 + cb];
            const float c2v = sc3[(k * 4 + 2) * 64 + cb];
            const float c3v = sc3[(k * 4 + 3) * 64 + cb];
            float s2 = __fmul_rn(c0, c0);
            s2 = __fadd_rn(s2, __fmul_rn(c1, c1));
            s2 = __fadd_rn(s2, __fmul_rn(c2v, c2v));
            s2 = __fadd_rn(s2, __fmul_rn(c3v, c3v));
            float d = __fmaf_rn(v.x, c0, 0.0f);
            d = __fmaf_rn(v.y, c1, d);
            d = __fmaf_rn(v.z, c2v, d);
            d = __fmaf_rn(v.w, c3v, d);
            const float s = __fadd_rn(s2, -__fmul_rn(2.0f, d));
            if (s < best) { best = s; bik = k; }
        }
        ((unsigned char*)g_idx3)[(start + p) * 64 + cb] = (unsigned char)bik;
    }
}

// ===================================================================
// accum3: flat sum, 296 blocks (148 tiles x 2 oh), SMALL CHUNKS:
// chunk = 1 cb x 512 o = 32 KB -> smem 92160 -> 2 blocks/SM, one wave.
// 512 threads = 128 og x 4 ps. dyn smem = 92160 (tr overlay needs it).
// ===================================================================
__global__ void __launch_bounds__(512, 2) k_accum3(const float* __restrict__ lut,
                                                   const float* __restrict__ scale,
                                                   const float* __restrict__ bias,
                                                   const float* __restrict__ xin,
                                                   float* __restrict__ out) {
    extern __shared__ float sm[];
    float* lutS = sm;                                        // 2 * 8192 floats
    unsigned char* idxB = (unsigned char*)(sm + 2 * 8192);   // cnt*64 bytes
    const int gx = blockIdx.x, t = threadIdx.x;
    const int tile = gx >> 1, oh = gx & 1;
    const int cnt = (tile < 56) ? 43 : 42;
    const int start = (tile < 56) ? tile * 43 : 56 * 43 + (tile - 56) * 42;
    const int og = t & 127, ps = t >> 7;
    const unsigned int* gi = (const unsigned int*)((const unsigned char*)g_idx3 + start * 64);
    for (int i = t; i < cnt * 16; i += 512) ((unsigned int*)idxB)[i] = gi[i];
    float4 acc[11];
#pragma unroll
    for (int i = 0; i < 11; i++) acc[i] = make_float4(0.f, 0.f, 0.f, 0.f);
    const unsigned int sbase = (unsigned int)__cvta_generic_to_shared(lutS);
    const float4* gl = (const float4*)lut;                   // row = 256 float4
    const int ob = oh * 128;                                 // float4 offset of half
#pragma unroll
    for (int i = 0; i < 4; i++) {
        const int e4 = i * 512 + t;                          // 0..2047
        const int row = e4 >> 7, c4 = e4 & 127;
        cp16(sbase + e4 * 16, (const void*)(gl + row * 256 + ob + c4));
    }
    cpcommit();
    int buf = 0;
    for (int ch = 0; ch < 64; ch++) {
        if (ch + 1 < 64) {
            const unsigned int d0 = sbase + (unsigned int)(buf ^ 1) * 32768u;
#pragma unroll
            for (int i = 0; i < 4; i++) {
                const int e4 = i * 512 + t;
                const int row = e4 >> 7, c4 = e4 & 127;
                cp16(d0 + e4 * 16, (const void*)(gl + ((ch + 1) * 16 + row) * 256 + ob + c4));
            }
            cpcommit();
            cpwait1();
        } else {
            cpwait0();
        }
        __syncthreads();
        const float* L = lutS + buf * 8192;                  // 16 rows x 512 floats
#pragma unroll
        for (int i = 0; i < 11; i++) {
            const int p = ps + 4 * i;
            if (p < cnt) {
                const unsigned int k = idxB[p * 64 + ch];
                const float4 lv = *(const float4*)(L + (k << 9) + (og << 2));
                acc[i].x = __fadd_rn(acc[i].x, lv.x);
                acc[i].y = __fadd_rn(acc[i].y, lv.y);
                acc[i].z = __fadd_rn(acc[i].z, lv.z);
                acc[i].w = __fadd_rn(acc[i].w, lv.w);
            }
        }
        __syncthreads();
        buf ^= 1;
    }
    float* tr = lutS;   // 512*45 floats = 92160 B (overlays everything)
    __syncthreads();
#pragma unroll
    for (int i = 0; i < 11; i++) {
        const int p = ps + 4 * i;
        if (p < cnt) {
            tr[(og * 4 + 0) * 45 + p] = acc[i].x;
            tr[(og * 4 + 1) * 45 + p] = acc[i].y;
            tr[(og * 4 + 2) * 45 + p] = acc[i].z;
            tr[(og * 4 + 3) * 45 + p] = acc[i].w;
        }
    }
    __syncthreads();
    {
        const int ol = t;
        if (ol < 512) {
            const int O = oh * 512 + ol;
            const float scv = scale[O], biv = bias[O];
            const float* trr = tr + ol * 45;
            for (int p = 0; p < cnt; p++) {
                const int P = start + p;
                const int bb = P / 196, pp = P % 196;
                const int addr = (bb * 1024 + O) * PP + pp;
                float r = __fadd_rn(__fadd_rn(__fmul_rn(trr[p], scv), biv), xin[addr]);
                out[addr] = fmaxf(r, 0.0f);
            }
        }
    }
}

extern "C" void kernel_launch(void* const* d_in, const int* in_sizes, int n_in,
                              void* d_out, int out_size) {
    const float* x   = (const float*)d_in[0];
    const float* c1c = (const float*)d_in[1];
    const float* c1l = (const float*)d_in[2];
    const float* c1s = (const float*)d_in[3];
    const float* c1b = (const float*)d_in[4];
    const float* c2c = (const float*)d_in[5];
    const float* c2l = (const float*)d_in[6];
    const float* c2s = (const float*)d_in[7];
    const float* c2b = (const float*)d_in[8];
    const float* c3c = (const float*)d_in[9];
    const float* c3l = (const float*)d_in[10];
    const float* c3s = (const float*)d_in[11];
    const float* c3b = (const float*)d_in[12];
    float* out = (float*)d_out;

    cudaFuncSetAttribute(k_encode1,  cudaFuncAttributeMaxDynamicSharedMemorySize, 57344);
    cudaFuncSetAttribute(k_encode2,  cudaFuncAttributeMaxDynamicSharedMemorySize, 73728);
    cudaFuncSetAttribute(k_accum_l1, cudaFuncAttributeMaxDynamicSharedMemorySize, 76544);
    cudaFuncSetAttribute(k_accum_l2f, cudaFuncAttributeMaxDynamicSharedMemorySize, 158464);
    cudaFuncSetAttribute(k_accum3,   cudaFuncAttributeMaxDynamicSharedMemorySize, 92160);

    k_encode1<<<dim3(NH, BB), 256, 57344>>>(x, c1c);
    k_accum_l1<<<dim3(296), 512, 76544>>>(c1l, c1s, c1b);
    k_encode2<<<dim3(NH, BB), 256, 73728>>>(c2c);
    k_accum_l2f<<<dim3(148), 512, 158464>>>(c2l, c2s, c2b, c3c);
    k_accum3<<<dim3(296), 512, 92160>>>(c3l, c3s, c3b, x, out);
    (void)in_sizes; (void)n_in; (void)out_size;
}